// round 14
// baseline (speedup 1.0000x reference)
#include <cuda_runtime.h>
#include <cuda_fp16.h>
#include <cstdint>

#define NMAX 100000
#define EMAX 800000
#define HID 64

// ---------------- scratch (device globals) ----------------
__device__ __half g_h0h[NMAX * HID];        // fc output (fp16)
__device__ __half g_h1h[NMAX * HID];        // layer-1 output (fp16)
__device__ __half g_msg1[NMAX * HID];       // layer-1 messages h0@w1 (UNscaled, fp16)
__device__ __half g_msg2[NMAX * HID];       // layer-2 messages (h1@w2)*norm_out (fp16)
__device__ int   g_deg_out[NMAX];
__device__ int   g_deg_in[NMAX];
__device__ float g_norm_out[NMAX];
__device__ float g_norm_in[NMAX];
__device__ int   g_rowstart[NMAX];
__device__ int   g_cursor[NMAX];
__device__ int   g_csr_src[EMAX];
__device__ int   g_total;
__device__ unsigned int g_bar;
__device__ float g_stats[2 * HID];

__device__ __forceinline__ float scale_const() { return 0.70710678118654752440f; }

__device__ __forceinline__ uint2 pack_half4(float a, float b, float c, float d) {
    __half2 p0 = __floats2half2_rn(a, b);
    __half2 p1 = __floats2half2_rn(c, d);
    uint2 u;
    u.x = *reinterpret_cast<unsigned int*>(&p0);
    u.y = *reinterpret_cast<unsigned int*>(&p1);
    return u;
}

// ---------------- graph build chain (side stream) ----------------
__global__ void zero_all_kernel(int n_nodes) {
    int idx = blockIdx.x * blockDim.x + threadIdx.x;
    if (idx < n_nodes) { g_deg_out[idx] = 0; g_deg_in[idx] = 0; }
    if (idx < 2 * HID) g_stats[idx] = 0.f;
    if (idx == 0) { g_total = 0; g_bar = 0u; }
}

__global__ void degree_kernel(const int* __restrict__ src, const int* __restrict__ dst, int n_edges) {
    int e = blockIdx.x * blockDim.x + threadIdx.x;
    if (e < n_edges) {
        atomicAdd(&g_deg_out[src[e]], 1);
        atomicAdd(&g_deg_in[dst[e]], 1);
    }
}

__global__ void finalize_kernel(int n_nodes) {
    int n = blockIdx.x * blockDim.x + threadIdx.x;
    if (n < n_nodes) {
        int deg = g_deg_in[n];
        int start = atomicAdd(&g_total, deg);
        g_rowstart[n] = start;
        g_cursor[n] = start;
        int dov = g_deg_out[n]; if (dov < 1) dov = 1;
        int din = deg; if (din < 1) din = 1;
        g_norm_out[n] = rsqrtf((float)dov);
        g_norm_in[n]  = rsqrtf((float)din);
    }
}

__global__ void bin_kernel(const int* __restrict__ src, const int* __restrict__ dst, int n_edges) {
    int e = blockIdx.x * blockDim.x + threadIdx.x;
    if (e < n_edges) {
        int p = atomicAdd(&g_cursor[dst[e]], 1);
        g_csr_src[p] = src[e];
    }
}

// ======================================================================
// Fused fc + gemm1 (graph-independent), fp32 FMA, 128-row tiles:
//   h0 = x @ fc_w + fc_b   -> g_h0h (fp16)
//   msg1 = h0 @ w1         -> g_msg1 (fp16)
// ======================================================================
__global__ __launch_bounds__(256) void fcg1_kernel(const float* __restrict__ x,
                                                   const float* __restrict__ fcw,
                                                   const float* __restrict__ fcb,
                                                   const float* __restrict__ w1,
                                                   int n_nodes) {
    __shared__ float sXT[64][132];
    __shared__ float sW[64][64];
    int br = blockIdx.x * 128;
    int tid = threadIdx.x;
    int tx = tid & 15, ty = tid >> 4;
    int r0 = ty * 8, j0 = tx * 4;
    int lc4 = tid & 15, lr0 = tid >> 4;

    float4 acc[8];
    #pragma unroll
    for (int i = 0; i < 8; i++) acc[i] = make_float4(0.f, 0.f, 0.f, 0.f);

    for (int kc = 0; kc < 2; kc++) {
        if (kc) __syncthreads();
        for (int i = tid; i < 1024; i += 256) {
            int k = i >> 4, c = (i & 15) << 2;
            *(float4*)&sW[k][c] = *(const float4*)&fcw[(kc * 64 + k) * 64 + c];
        }
        #pragma unroll
        for (int t = 0; t < 8; t++) {
            int r = lr0 + t * 16;
            int row = br + r;
            float4 v = make_float4(0.f, 0.f, 0.f, 0.f);
            if (row < n_nodes) v = *(const float4*)&x[row * 128 + kc * 64 + (lc4 << 2)];
            sXT[lc4 * 4 + ((0 + lc4) & 3)][r] = v.x;
            sXT[lc4 * 4 + ((1 + lc4) & 3)][r] = v.y;
            sXT[lc4 * 4 + ((2 + lc4) & 3)][r] = v.z;
            sXT[lc4 * 4 + ((3 + lc4) & 3)][r] = v.w;
        }
        __syncthreads();
        #pragma unroll 4
        for (int c = 0; c < 16; c++) {
            #pragma unroll
            for (int j = 0; j < 4; j++) {
                int klog = c * 4 + j;
                int kp   = c * 4 + ((j + c) & 3);
                float4 wv = *(float4*)&sW[klog][j0];
                float4 a0 = *(float4*)&sXT[kp][r0];
                float4 a1 = *(float4*)&sXT[kp][r0 + 4];
                acc[0].x = fmaf(a0.x, wv.x, acc[0].x); acc[0].y = fmaf(a0.x, wv.y, acc[0].y);
                acc[0].z = fmaf(a0.x, wv.z, acc[0].z); acc[0].w = fmaf(a0.x, wv.w, acc[0].w);
                acc[1].x = fmaf(a0.y, wv.x, acc[1].x); acc[1].y = fmaf(a0.y, wv.y, acc[1].y);
                acc[1].z = fmaf(a0.y, wv.z, acc[1].z); acc[1].w = fmaf(a0.y, wv.w, acc[1].w);
                acc[2].x = fmaf(a0.z, wv.x, acc[2].x); acc[2].y = fmaf(a0.z, wv.y, acc[2].y);
                acc[2].z = fmaf(a0.z, wv.z, acc[2].z); acc[2].w = fmaf(a0.z, wv.w, acc[2].w);
                acc[3].x = fmaf(a0.w, wv.x, acc[3].x); acc[3].y = fmaf(a0.w, wv.y, acc[3].y);
                acc[3].z = fmaf(a0.w, wv.z, acc[3].z); acc[3].w = fmaf(a0.w, wv.w, acc[3].w);
                acc[4].x = fmaf(a1.x, wv.x, acc[4].x); acc[4].y = fmaf(a1.x, wv.y, acc[4].y);
                acc[4].z = fmaf(a1.x, wv.z, acc[4].z); acc[4].w = fmaf(a1.x, wv.w, acc[4].w);
                acc[5].x = fmaf(a1.y, wv.x, acc[5].x); acc[5].y = fmaf(a1.y, wv.y, acc[5].y);
                acc[5].z = fmaf(a1.y, wv.z, acc[5].z); acc[5].w = fmaf(a1.y, wv.w, acc[5].w);
                acc[6].x = fmaf(a1.z, wv.x, acc[6].x); acc[6].y = fmaf(a1.z, wv.y, acc[6].y);
                acc[6].z = fmaf(a1.z, wv.z, acc[6].z); acc[6].w = fmaf(a1.z, wv.w, acc[6].w);
                acc[7].x = fmaf(a1.w, wv.x, acc[7].x); acc[7].y = fmaf(a1.w, wv.y, acc[7].y);
                acc[7].z = fmaf(a1.w, wv.z, acc[7].z); acc[7].w = fmaf(a1.w, wv.w, acc[7].w);
            }
        }
    }

    __syncthreads();
    {
        float4 bv = *(const float4*)&fcb[j0];
        #pragma unroll
        for (int i = 0; i < 8; i++) {
            int row = br + r0 + i;
            float4 o;
            o.x = acc[i].x + bv.x; o.y = acc[i].y + bv.y;
            o.z = acc[i].z + bv.z; o.w = acc[i].w + bv.w;
            if (row < n_nodes)
                reinterpret_cast<uint2*>(g_h0h)[row * 16 + tx] = pack_half4(o.x, o.y, o.z, o.w);
            else { o = make_float4(0.f, 0.f, 0.f, 0.f); }
            sXT[tx * 4 + ((0 + tx) & 3)][r0 + i] = o.x;
            sXT[tx * 4 + ((1 + tx) & 3)][r0 + i] = o.y;
            sXT[tx * 4 + ((2 + tx) & 3)][r0 + i] = o.z;
            sXT[tx * 4 + ((3 + tx) & 3)][r0 + i] = o.w;
        }
    }
    for (int i = tid; i < 1024; i += 256) {
        int k = i >> 4, c = (i & 15) << 2;
        *(float4*)&sW[k][c] = *(const float4*)&w1[k * 64 + c];
    }
    __syncthreads();

    #pragma unroll
    for (int i = 0; i < 8; i++) acc[i] = make_float4(0.f, 0.f, 0.f, 0.f);
    #pragma unroll 4
    for (int c = 0; c < 16; c++) {
        #pragma unroll
        for (int j = 0; j < 4; j++) {
            int klog = c * 4 + j;
            int kp   = c * 4 + ((j + c) & 3);
            float4 wv = *(float4*)&sW[klog][j0];
            float4 a0 = *(float4*)&sXT[kp][r0];
            float4 a1 = *(float4*)&sXT[kp][r0 + 4];
            acc[0].x = fmaf(a0.x, wv.x, acc[0].x); acc[0].y = fmaf(a0.x, wv.y, acc[0].y);
            acc[0].z = fmaf(a0.x, wv.z, acc[0].z); acc[0].w = fmaf(a0.x, wv.w, acc[0].w);
            acc[1].x = fmaf(a0.y, wv.x, acc[1].x); acc[1].y = fmaf(a0.y, wv.y, acc[1].y);
            acc[1].z = fmaf(a0.y, wv.z, acc[1].z); acc[1].w = fmaf(a0.y, wv.w, acc[1].w);
            acc[2].x = fmaf(a0.z, wv.x, acc[2].x); acc[2].y = fmaf(a0.z, wv.y, acc[2].y);
            acc[2].z = fmaf(a0.z, wv.z, acc[2].z); acc[2].w = fmaf(a0.z, wv.w, acc[2].w);
            acc[3].x = fmaf(a0.w, wv.x, acc[3].x); acc[3].y = fmaf(a0.w, wv.y, acc[3].y);
            acc[3].z = fmaf(a0.w, wv.z, acc[3].z); acc[3].w = fmaf(a0.w, wv.w, acc[3].w);
            acc[4].x = fmaf(a1.x, wv.x, acc[4].x); acc[4].y = fmaf(a1.x, wv.y, acc[4].y);
            acc[4].z = fmaf(a1.x, wv.z, acc[4].z); acc[4].w = fmaf(a1.x, wv.w, acc[4].w);
            acc[5].x = fmaf(a1.y, wv.x, acc[5].x); acc[5].y = fmaf(a1.y, wv.y, acc[5].y);
            acc[5].z = fmaf(a1.y, wv.z, acc[5].z); acc[5].w = fmaf(a1.y, wv.w, acc[5].w);
            acc[6].x = fmaf(a1.z, wv.x, acc[6].x); acc[6].y = fmaf(a1.z, wv.y, acc[6].y);
            acc[6].z = fmaf(a1.z, wv.z, acc[6].z); acc[6].w = fmaf(a1.z, wv.w, acc[6].w);
            acc[7].x = fmaf(a1.w, wv.x, acc[7].x); acc[7].y = fmaf(a1.w, wv.y, acc[7].y);
            acc[7].z = fmaf(a1.w, wv.z, acc[7].z); acc[7].w = fmaf(a1.w, wv.w, acc[7].w);
        }
    }
    #pragma unroll
    for (int i = 0; i < 8; i++) {
        int row = br + r0 + i;
        if (row < n_nodes)
            reinterpret_cast<uint2*>(g_msg1)[row * 16 + tx] =
                pack_half4(acc[i].x, acc[i].y, acc[i].z, acc[i].w);
    }
}

// ======================================================================
// Persistent kernel (grid MUST be 592 = 148 SMs x 4 blocks, single wave):
//  phase 1: 64-row tiles; gather = WARP PER NODE (no divergence) -> g_h1h,
//           then tile gemm2 -> g_msg2 (pre-scaled by norm_out)
//  [device barrier]
//  phase 2: warp-per-node layer-2 aggregation + epilogue -> out, BN stats
//  [device barrier]
//  phase 3: BN apply on out
// ======================================================================
__global__ __launch_bounds__(256, 4) void fused_tail_kernel(const float* __restrict__ b1,
                                                            const float* __restrict__ w2,
                                                            const float* __restrict__ b2,
                                                            const float* __restrict__ gamma,
                                                            const float* __restrict__ beta,
                                                            float* __restrict__ out,
                                                            int n_nodes) {
    __shared__ float sHT[64][68];
    __shared__ float sW[64][64];
    int tid = threadIdx.x;
    int tx = tid & 15, ty = tid >> 4;
    int r0 = ty * 4, j0 = tx * 4;
    int warp = tid >> 5, lane = tid & 31;
    const float sc = scale_const();
    const __half2* __restrict__ m1h = reinterpret_cast<const __half2*>(g_msg1);

    // w2 into smem once
    for (int i = tid; i < 1024; i += 256) {
        int k = i >> 4, c = (i & 15) << 2;
        *(float4*)&sW[k][c] = *(const float4*)&w2[k * 64 + c];
    }

    // swizzled physical rows for this lane's two columns
    int c0 = lane * 2, c1 = lane * 2 + 1;
    int p0 = (c0 & ~3) + (((c0 & 3) + (c0 >> 2)) & 3);
    int p1 = (c1 & ~3) + (((c1 & 3) + (c1 >> 2)) & 3);

    // ---------------- phase 1: warp-per-node gather + tile gemm2 ----------------
    int ntiles = (n_nodes + 63) / 64;
    float2 bv1 = *(const float2*)&b1[lane * 2];
    for (int tile = blockIdx.x; tile < ntiles; tile += gridDim.x) {
        int br = tile * 64;
        __syncthreads();   // previous tile's gemm reads done before refill
        #pragma unroll
        for (int rr = warp; rr < 64; rr += 8) {
            int row = br + rr;
            float2 v = make_float2(0.f, 0.f);
            if (row < n_nodes) {
                int beg = g_rowstart[row];
                int end = beg + g_deg_in[row];
                float2 a0 = make_float2(0.f, 0.f);
                float2 a1 = make_float2(0.f, 0.f);
                int e = beg;
                for (; e + 4 <= end; e += 4) {
                    int s0 = g_csr_src[e], s1 = g_csr_src[e + 1];
                    int s2 = g_csr_src[e + 2], s3 = g_csr_src[e + 3];
                    float n0 = g_norm_out[s0], n1 = g_norm_out[s1];
                    float n2 = g_norm_out[s2], n3 = g_norm_out[s3];
                    float2 q0 = __half22float2(m1h[s0 * 32 + lane]);
                    float2 q1 = __half22float2(m1h[s1 * 32 + lane]);
                    float2 q2 = __half22float2(m1h[s2 * 32 + lane]);
                    float2 q3 = __half22float2(m1h[s3 * 32 + lane]);
                    a0.x = fmaf(q0.x, n0, a0.x); a0.y = fmaf(q0.y, n0, a0.y);
                    a1.x = fmaf(q1.x, n1, a1.x); a1.y = fmaf(q1.y, n1, a1.y);
                    a0.x = fmaf(q2.x, n2, a0.x); a0.y = fmaf(q2.y, n2, a0.y);
                    a1.x = fmaf(q3.x, n3, a1.x); a1.y = fmaf(q3.y, n3, a1.y);
                }
                for (; e < end; e++) {
                    int s = g_csr_src[e];
                    float ns = g_norm_out[s];
                    float2 q = __half22float2(m1h[s * 32 + lane]);
                    a0.x = fmaf(q.x, ns, a0.x); a0.y = fmaf(q.y, ns, a0.y);
                }
                float ni = g_norm_in[row];
                float2 h0f = __half22float2(reinterpret_cast<const __half2*>(g_h0h)[row * 32 + lane]);
                v.x = (h0f.x + (a0.x + a1.x) * ni + bv1.x) * sc;
                v.y = (h0f.y + (a0.y + a1.y) * ni + bv1.y) * sc;
                reinterpret_cast<__half2*>(g_h1h)[row * 32 + lane] = __floats2half2_rn(v.x, v.y);
            }
            sHT[p0][rr] = v.x;
            sHT[p1][rr] = v.y;
        }
        __syncthreads();

        // gemm2: 4 rows x 4 cols per thread (16x16 mapping)
        float4 acc[4];
        #pragma unroll
        for (int i = 0; i < 4; i++) acc[i] = make_float4(0.f, 0.f, 0.f, 0.f);
        #pragma unroll 4
        for (int c = 0; c < 16; c++) {
            #pragma unroll
            for (int j = 0; j < 4; j++) {
                int klog = c * 4 + j;
                int kp   = c * 4 + ((j + c) & 3);
                float4 wv = *(float4*)&sW[klog][j0];
                float4 a0 = *(float4*)&sHT[kp][r0];
                acc[0].x = fmaf(a0.x, wv.x, acc[0].x); acc[0].y = fmaf(a0.x, wv.y, acc[0].y);
                acc[0].z = fmaf(a0.x, wv.z, acc[0].z); acc[0].w = fmaf(a0.x, wv.w, acc[0].w);
                acc[1].x = fmaf(a0.y, wv.x, acc[1].x); acc[1].y = fmaf(a0.y, wv.y, acc[1].y);
                acc[1].z = fmaf(a0.y, wv.z, acc[1].z); acc[1].w = fmaf(a0.y, wv.w, acc[1].w);
                acc[2].x = fmaf(a0.z, wv.x, acc[2].x); acc[2].y = fmaf(a0.z, wv.y, acc[2].y);
                acc[2].z = fmaf(a0.z, wv.z, acc[2].z); acc[2].w = fmaf(a0.z, wv.w, acc[2].w);
                acc[3].x = fmaf(a0.w, wv.x, acc[3].x); acc[3].y = fmaf(a0.w, wv.y, acc[3].y);
                acc[3].z = fmaf(a0.w, wv.z, acc[3].z); acc[3].w = fmaf(a0.w, wv.w, acc[3].w);
            }
        }
        #pragma unroll
        for (int i = 0; i < 4; i++) {
            int row = br + r0 + i;
            if (row < n_nodes) {
                float ns = g_norm_out[row];
                reinterpret_cast<uint2*>(g_msg2)[row * 16 + tx] =
                    pack_half4(acc[i].x * ns, acc[i].y * ns, acc[i].z * ns, acc[i].w * ns);
            }
        }
    }

    // ---------------- device barrier #1 ----------------
    __threadfence();
    __syncthreads();
    if (tid == 0) {
        atomicAdd(&g_bar, 1u);
        while (atomicAdd(&g_bar, 0u) < gridDim.x) __nanosleep(64);
        __threadfence();
    }
    __syncthreads();

    // ---------------- phase 2: warp-per-node layer-2 agg + epilogue + BN stats ----------------
    __shared__ float ssum[64], ssq[64];
    if (tid < 64) { ssum[tid] = 0.f; ssq[tid] = 0.f; }
    __syncthreads();
    {
        float2 bv = *(const float2*)&b2[lane * 2];
        float2 ls = make_float2(0.f, 0.f);
        float2 lq = make_float2(0.f, 0.f);
        const __half2* __restrict__ m2h = reinterpret_cast<const __half2*>(g_msg2);
        int gwarp = blockIdx.x * 8 + warp;
        int nwarps = gridDim.x * 8;

        for (int node = gwarp; node < n_nodes; node += nwarps) {
            int beg = g_rowstart[node];
            int end = beg + g_deg_in[node];
            float2 a0 = make_float2(0.f, 0.f);
            float2 a1 = make_float2(0.f, 0.f);
            int e = beg;
            for (; e + 4 <= end; e += 4) {
                int s0 = g_csr_src[e], s1 = g_csr_src[e + 1];
                int s2 = g_csr_src[e + 2], s3 = g_csr_src[e + 3];
                float2 q0 = __half22float2(m2h[s0 * 32 + lane]);
                float2 q1 = __half22float2(m2h[s1 * 32 + lane]);
                float2 q2 = __half22float2(m2h[s2 * 32 + lane]);
                float2 q3 = __half22float2(m2h[s3 * 32 + lane]);
                a0.x += q0.x; a0.y += q0.y;
                a1.x += q1.x; a1.y += q1.y;
                a0.x += q2.x; a0.y += q2.y;
                a1.x += q3.x; a1.y += q3.y;
            }
            for (; e < end; e++) {
                int s = g_csr_src[e];
                float2 q = __half22float2(m2h[s * 32 + lane]);
                a0.x += q.x; a0.y += q.y;
            }
            float ni = g_norm_in[node];
            float2 h1f = __half22float2(reinterpret_cast<const __half2*>(g_h1h)[node * 32 + lane]);
            float2 h2;
            h2.x = (h1f.x + (a0.x + a1.x) * ni + bv.x) * sc;
            h2.y = (h1f.y + (a0.y + a1.y) * ni + bv.y) * sc;
            reinterpret_cast<float2*>(out)[node * 32 + lane] = h2;
            ls.x += h2.x; ls.y += h2.y;
            lq.x += h2.x * h2.x; lq.y += h2.y * h2.y;
        }
        atomicAdd(&ssum[lane * 2 + 0], ls.x); atomicAdd(&ssq[lane * 2 + 0], lq.x);
        atomicAdd(&ssum[lane * 2 + 1], ls.y); atomicAdd(&ssq[lane * 2 + 1], lq.y);
    }
    __syncthreads();
    if (tid < 64) {
        atomicAdd(&g_stats[tid], ssum[tid]);
        atomicAdd(&g_stats[64 + tid], ssq[tid]);
    }

    // ---------------- device barrier #2 ----------------
    __threadfence();
    __syncthreads();
    if (tid == 0) {
        atomicAdd(&g_bar, 1u);
        while (atomicAdd(&g_bar, 0u) < 2u * gridDim.x) __nanosleep(64);
        __threadfence();
    }
    __syncthreads();

    // ---------------- phase 3: BN apply ----------------
    __shared__ float s_scale[64], s_shift[64];
    if (tid < 64) {
        int j = tid;
        volatile float* vs = g_stats;
        float inv_n = 1.f / (float)n_nodes;
        float mu = vs[j] * inv_n;
        float var = vs[64 + j] * inv_n - mu * mu;
        if (var < 0.f) var = 0.f;
        float g = rsqrtf(var + 1e-5f) * gamma[j];
        s_scale[j] = g;
        s_shift[j] = beta[j] - mu * g;
    }
    __syncthreads();
    int total4 = n_nodes * 16;
    int stride = gridDim.x * blockDim.x;
    for (int i = blockIdx.x * blockDim.x + tid; i < total4; i += stride) {
        float4 v = reinterpret_cast<float4*>(out)[i];
        int jj = (i & 15) << 2;
        v.x = v.x * s_scale[jj + 0] + s_shift[jj + 0];
        v.y = v.y * s_scale[jj + 1] + s_shift[jj + 1];
        v.z = v.z * s_scale[jj + 2] + s_shift[jj + 2];
        v.w = v.w * s_scale[jj + 3] + s_shift[jj + 3];
        reinterpret_cast<float4*>(out)[i] = v;
    }
}

// ---------------- launch ----------------
extern "C" void kernel_launch(void* const* d_in, const int* in_sizes, int n_in,
                              void* d_out, int out_size) {
    const int*   src   = (const int*)d_in[0];
    const int*   dst   = (const int*)d_in[1];
    const float* x     = (const float*)d_in[2];
    const float* fc_w  = (const float*)d_in[3];
    const float* fc_b  = (const float*)d_in[4];
    const float* w1    = (const float*)d_in[5];
    const float* b1    = (const float*)d_in[6];
    const float* w2    = (const float*)d_in[7];
    const float* b2    = (const float*)d_in[8];
    const float* gamma = (const float*)d_in[9];
    const float* beta  = (const float*)d_in[10];
    float* out = (float*)d_out;

    int n_edges = in_sizes[0];
    int n_nodes = in_sizes[2] / 128;

    static cudaStream_t s_build = nullptr;
    static cudaEvent_t ev_fork = nullptr, ev_join = nullptr;
    if (s_build == nullptr) {
        cudaStreamCreateWithFlags(&s_build, cudaStreamNonBlocking);
        cudaEventCreateWithFlags(&ev_fork, cudaEventDisableTiming);
        cudaEventCreateWithFlags(&ev_join, cudaEventDisableTiming);
    }

    cudaEventRecord(ev_fork, 0);
    cudaStreamWaitEvent(s_build, ev_fork, 0);
    zero_all_kernel<<<(n_nodes + 255) / 256, 256, 0, s_build>>>(n_nodes);
    degree_kernel<<<(n_edges + 255) / 256, 256, 0, s_build>>>(src, dst, n_edges);
    finalize_kernel<<<(n_nodes + 255) / 256, 256, 0, s_build>>>(n_nodes);
    bin_kernel<<<(n_edges + 255) / 256, 256, 0, s_build>>>(src, dst, n_edges);
    cudaEventRecord(ev_join, s_build);

    int gblocks = (n_nodes + 127) / 128;
    fcg1_kernel<<<gblocks, 256>>>(x, fc_w, fc_b, w1, n_nodes);

    cudaStreamWaitEvent(0, ev_join, 0);
    fused_tail_kernel<<<592, 256>>>(b1, w2, b2, gamma, beta, out, n_nodes);
}

// round 15
// speedup vs baseline: 1.1210x; 1.1210x over previous
#include <cuda_runtime.h>
#include <cuda_fp16.h>
#include <cstdint>

#define NMAX 100000
#define EMAX 800000
#define HID 64

// ---------------- scratch (device globals) ----------------
__device__ __half g_h0h[NMAX * HID];        // fc output (fp16)
__device__ __half g_h1h[NMAX * HID];        // layer-1 output (fp16)
__device__ __half g_msg1[NMAX * HID];       // layer-1 messages h0@w1 (UNscaled, fp16)
__device__ __half g_msg2[NMAX * HID];       // layer-2 messages (h1@w2)*norm_out (fp16)
__device__ int   g_deg_out[NMAX];
__device__ int   g_deg_in[NMAX];
__device__ float g_norm_out[NMAX];
__device__ float g_norm_in[NMAX];
__device__ int   g_rowstart[NMAX];
__device__ int   g_cursor[NMAX];
__device__ int   g_csr_src[EMAX];
__device__ int   g_total;
__device__ unsigned int g_bar;
__device__ float g_stats[2 * HID];

__device__ __forceinline__ float scale_const() { return 0.70710678118654752440f; }

__device__ __forceinline__ uint2 pack_half4(float a, float b, float c, float d) {
    __half2 p0 = __floats2half2_rn(a, b);
    __half2 p1 = __floats2half2_rn(c, d);
    uint2 u;
    u.x = *reinterpret_cast<unsigned int*>(&p0);
    u.y = *reinterpret_cast<unsigned int*>(&p1);
    return u;
}
__device__ __forceinline__ void unpack_half4(uint2 u, float2& f0, float2& f1) {
    __half2 h0 = *reinterpret_cast<__half2*>(&u.x);
    __half2 h1 = *reinterpret_cast<__half2*>(&u.y);
    f0 = __half22float2(h0);
    f1 = __half22float2(h1);
}

// ---------------- graph build chain (side stream) ----------------
__global__ void zero_all_kernel(int n_nodes) {
    int idx = blockIdx.x * blockDim.x + threadIdx.x;
    if (idx < n_nodes) { g_deg_out[idx] = 0; g_deg_in[idx] = 0; }
    if (idx < 2 * HID) g_stats[idx] = 0.f;
    if (idx == 0) { g_total = 0; g_bar = 0u; }
}

__global__ void degree_kernel(const int* __restrict__ src, const int* __restrict__ dst, int n_edges) {
    int e = blockIdx.x * blockDim.x + threadIdx.x;
    if (e < n_edges) {
        atomicAdd(&g_deg_out[src[e]], 1);
        atomicAdd(&g_deg_in[dst[e]], 1);
    }
}

__global__ void finalize_kernel(int n_nodes) {
    int n = blockIdx.x * blockDim.x + threadIdx.x;
    if (n < n_nodes) {
        int deg = g_deg_in[n];
        int start = atomicAdd(&g_total, deg);
        g_rowstart[n] = start;
        g_cursor[n] = start;
        int dov = g_deg_out[n]; if (dov < 1) dov = 1;
        int din = deg; if (din < 1) din = 1;
        g_norm_out[n] = rsqrtf((float)dov);
        g_norm_in[n]  = rsqrtf((float)din);
    }
}

__global__ void bin_kernel(const int* __restrict__ src, const int* __restrict__ dst, int n_edges) {
    int e = blockIdx.x * blockDim.x + threadIdx.x;
    if (e < n_edges) {
        int p = atomicAdd(&g_cursor[dst[e]], 1);
        g_csr_src[p] = src[e];
    }
}

// ======================================================================
// Fused fc + gemm1 (graph-independent), fp32 FMA, 128-row tiles:
//   h0 = x @ fc_w + fc_b   -> g_h0h (fp16)
//   msg1 = h0 @ w1         -> g_msg1 (fp16)
// ======================================================================
__global__ __launch_bounds__(256) void fcg1_kernel(const float* __restrict__ x,
                                                   const float* __restrict__ fcw,
                                                   const float* __restrict__ fcb,
                                                   const float* __restrict__ w1,
                                                   int n_nodes) {
    __shared__ float sXT[64][132];
    __shared__ float sW[64][64];
    int br = blockIdx.x * 128;
    int tid = threadIdx.x;
    int tx = tid & 15, ty = tid >> 4;
    int r0 = ty * 8, j0 = tx * 4;
    int lc4 = tid & 15, lr0 = tid >> 4;

    float4 acc[8];
    #pragma unroll
    for (int i = 0; i < 8; i++) acc[i] = make_float4(0.f, 0.f, 0.f, 0.f);

    for (int kc = 0; kc < 2; kc++) {
        if (kc) __syncthreads();
        for (int i = tid; i < 1024; i += 256) {
            int k = i >> 4, c = (i & 15) << 2;
            *(float4*)&sW[k][c] = *(const float4*)&fcw[(kc * 64 + k) * 64 + c];
        }
        #pragma unroll
        for (int t = 0; t < 8; t++) {
            int r = lr0 + t * 16;
            int row = br + r;
            float4 v = make_float4(0.f, 0.f, 0.f, 0.f);
            if (row < n_nodes) v = *(const float4*)&x[row * 128 + kc * 64 + (lc4 << 2)];
            sXT[lc4 * 4 + ((0 + lc4) & 3)][r] = v.x;
            sXT[lc4 * 4 + ((1 + lc4) & 3)][r] = v.y;
            sXT[lc4 * 4 + ((2 + lc4) & 3)][r] = v.z;
            sXT[lc4 * 4 + ((3 + lc4) & 3)][r] = v.w;
        }
        __syncthreads();
        #pragma unroll 4
        for (int c = 0; c < 16; c++) {
            #pragma unroll
            for (int j = 0; j < 4; j++) {
                int klog = c * 4 + j;
                int kp   = c * 4 + ((j + c) & 3);
                float4 wv = *(float4*)&sW[klog][j0];
                float4 a0 = *(float4*)&sXT[kp][r0];
                float4 a1 = *(float4*)&sXT[kp][r0 + 4];
                acc[0].x = fmaf(a0.x, wv.x, acc[0].x); acc[0].y = fmaf(a0.x, wv.y, acc[0].y);
                acc[0].z = fmaf(a0.x, wv.z, acc[0].z); acc[0].w = fmaf(a0.x, wv.w, acc[0].w);
                acc[1].x = fmaf(a0.y, wv.x, acc[1].x); acc[1].y = fmaf(a0.y, wv.y, acc[1].y);
                acc[1].z = fmaf(a0.y, wv.z, acc[1].z); acc[1].w = fmaf(a0.y, wv.w, acc[1].w);
                acc[2].x = fmaf(a0.z, wv.x, acc[2].x); acc[2].y = fmaf(a0.z, wv.y, acc[2].y);
                acc[2].z = fmaf(a0.z, wv.z, acc[2].z); acc[2].w = fmaf(a0.z, wv.w, acc[2].w);
                acc[3].x = fmaf(a0.w, wv.x, acc[3].x); acc[3].y = fmaf(a0.w, wv.y, acc[3].y);
                acc[3].z = fmaf(a0.w, wv.z, acc[3].z); acc[3].w = fmaf(a0.w, wv.w, acc[3].w);
                acc[4].x = fmaf(a1.x, wv.x, acc[4].x); acc[4].y = fmaf(a1.x, wv.y, acc[4].y);
                acc[4].z = fmaf(a1.x, wv.z, acc[4].z); acc[4].w = fmaf(a1.x, wv.w, acc[4].w);
                acc[5].x = fmaf(a1.y, wv.x, acc[5].x); acc[5].y = fmaf(a1.y, wv.y, acc[5].y);
                acc[5].z = fmaf(a1.y, wv.z, acc[5].z); acc[5].w = fmaf(a1.y, wv.w, acc[5].w);
                acc[6].x = fmaf(a1.z, wv.x, acc[6].x); acc[6].y = fmaf(a1.z, wv.y, acc[6].y);
                acc[6].z = fmaf(a1.z, wv.z, acc[6].z); acc[6].w = fmaf(a1.z, wv.w, acc[6].w);
                acc[7].x = fmaf(a1.w, wv.x, acc[7].x); acc[7].y = fmaf(a1.w, wv.y, acc[7].y);
                acc[7].z = fmaf(a1.w, wv.z, acc[7].z); acc[7].w = fmaf(a1.w, wv.w, acc[7].w);
            }
        }
    }

    __syncthreads();
    {
        float4 bv = *(const float4*)&fcb[j0];
        #pragma unroll
        for (int i = 0; i < 8; i++) {
            int row = br + r0 + i;
            float4 o;
            o.x = acc[i].x + bv.x; o.y = acc[i].y + bv.y;
            o.z = acc[i].z + bv.z; o.w = acc[i].w + bv.w;
            if (row < n_nodes)
                reinterpret_cast<uint2*>(g_h0h)[row * 16 + tx] = pack_half4(o.x, o.y, o.z, o.w);
            else { o = make_float4(0.f, 0.f, 0.f, 0.f); }
            sXT[tx * 4 + ((0 + tx) & 3)][r0 + i] = o.x;
            sXT[tx * 4 + ((1 + tx) & 3)][r0 + i] = o.y;
            sXT[tx * 4 + ((2 + tx) & 3)][r0 + i] = o.z;
            sXT[tx * 4 + ((3 + tx) & 3)][r0 + i] = o.w;
        }
    }
    for (int i = tid; i < 1024; i += 256) {
        int k = i >> 4, c = (i & 15) << 2;
        *(float4*)&sW[k][c] = *(const float4*)&w1[k * 64 + c];
    }
    __syncthreads();

    #pragma unroll
    for (int i = 0; i < 8; i++) acc[i] = make_float4(0.f, 0.f, 0.f, 0.f);
    #pragma unroll 4
    for (int c = 0; c < 16; c++) {
        #pragma unroll
        for (int j = 0; j < 4; j++) {
            int klog = c * 4 + j;
            int kp   = c * 4 + ((j + c) & 3);
            float4 wv = *(float4*)&sW[klog][j0];
            float4 a0 = *(float4*)&sXT[kp][r0];
            float4 a1 = *(float4*)&sXT[kp][r0 + 4];
            acc[0].x = fmaf(a0.x, wv.x, acc[0].x); acc[0].y = fmaf(a0.x, wv.y, acc[0].y);
            acc[0].z = fmaf(a0.x, wv.z, acc[0].z); acc[0].w = fmaf(a0.x, wv.w, acc[0].w);
            acc[1].x = fmaf(a0.y, wv.x, acc[1].x); acc[1].y = fmaf(a0.y, wv.y, acc[1].y);
            acc[1].z = fmaf(a0.y, wv.z, acc[1].z); acc[1].w = fmaf(a0.y, wv.w, acc[1].w);
            acc[2].x = fmaf(a0.z, wv.x, acc[2].x); acc[2].y = fmaf(a0.z, wv.y, acc[2].y);
            acc[2].z = fmaf(a0.z, wv.z, acc[2].z); acc[2].w = fmaf(a0.z, wv.w, acc[2].w);
            acc[3].x = fmaf(a0.w, wv.x, acc[3].x); acc[3].y = fmaf(a0.w, wv.y, acc[3].y);
            acc[3].z = fmaf(a0.w, wv.z, acc[3].z); acc[3].w = fmaf(a0.w, wv.w, acc[3].w);
            acc[4].x = fmaf(a1.x, wv.x, acc[4].x); acc[4].y = fmaf(a1.x, wv.y, acc[4].y);
            acc[4].z = fmaf(a1.x, wv.z, acc[4].z); acc[4].w = fmaf(a1.x, wv.w, acc[4].w);
            acc[5].x = fmaf(a1.y, wv.x, acc[5].x); acc[5].y = fmaf(a1.y, wv.y, acc[5].y);
            acc[5].z = fmaf(a1.y, wv.z, acc[5].z); acc[5].w = fmaf(a1.y, wv.w, acc[5].w);
            acc[6].x = fmaf(a1.z, wv.x, acc[6].x); acc[6].y = fmaf(a1.z, wv.y, acc[6].y);
            acc[6].z = fmaf(a1.z, wv.z, acc[6].z); acc[6].w = fmaf(a1.z, wv.w, acc[6].w);
            acc[7].x = fmaf(a1.w, wv.x, acc[7].x); acc[7].y = fmaf(a1.w, wv.y, acc[7].y);
            acc[7].z = fmaf(a1.w, wv.z, acc[7].z); acc[7].w = fmaf(a1.w, wv.w, acc[7].w);
        }
    }
    #pragma unroll
    for (int i = 0; i < 8; i++) {
        int row = br + r0 + i;
        if (row < n_nodes)
            reinterpret_cast<uint2*>(g_msg1)[row * 16 + tx] =
                pack_half4(acc[i].x, acc[i].y, acc[i].z, acc[i].w);
    }
}

// ======================================================================
// Persistent kernel (grid MUST be 592 = 148 SMs x 4 blocks, single wave):
//  phase 1: grid-stride 64-row tiles: CSR gather (msg1) + layer-1 epilogue
//           -> g_h1h, then gemm2 -> g_msg2 (pre-scaled by norm_out)
//  [device barrier]
//  phase 2: layer-2 aggregation + epilogue -> out, BN statistics
//  [device barrier]
//  phase 3: BN apply on out
// ======================================================================
__global__ __launch_bounds__(256, 4) void fused_tail_kernel(const float* __restrict__ b1,
                                                            const float* __restrict__ w2,
                                                            const float* __restrict__ b2,
                                                            const float* __restrict__ gamma,
                                                            const float* __restrict__ beta,
                                                            float* __restrict__ out,
                                                            int n_nodes) {
    __shared__ float sHT[64][68];
    __shared__ float sW[64][64];
    int tid = threadIdx.x;
    int tx = tid & 15, ty = tid >> 4;
    int r0 = ty * 4, j0 = tx * 4;
    int lc4 = tid & 15, lr0 = tid >> 4;
    const float sc = scale_const();
    const uint2* __restrict__ m1 = reinterpret_cast<const uint2*>(g_msg1);

    // w2 into smem once (sW untouched across tiles)
    for (int i = tid; i < 1024; i += 256) {
        int k = i >> 4, c = (i & 15) << 2;
        *(float4*)&sW[k][c] = *(const float4*)&w2[k * 64 + c];
    }

    // ---------------- phase 1: gather + gemm2 over 64-row tiles ----------------
    int ntiles = (n_nodes + 63) / 64;
    float4 bv1 = *(const float4*)&b1[lc4 << 2];
    for (int tile = blockIdx.x; tile < ntiles; tile += gridDim.x) {
        int br = tile * 64;
        __syncthreads();   // previous tile's gemm reads done before refill
        #pragma unroll
        for (int t = 0; t < 4; t++) {
            int r = lr0 + t * 16;
            int row = br + r;
            float4 v = make_float4(0.f, 0.f, 0.f, 0.f);
            if (row < n_nodes) {
                int beg = g_rowstart[row];
                int end = beg + g_deg_in[row];
                float4 a0 = make_float4(0.f, 0.f, 0.f, 0.f);
                float4 a1 = make_float4(0.f, 0.f, 0.f, 0.f);
                int e = beg;
                for (; e + 4 <= end; e += 4) {
                    int s0 = g_csr_src[e], s1 = g_csr_src[e + 1];
                    int s2 = g_csr_src[e + 2], s3 = g_csr_src[e + 3];
                    float n0 = g_norm_out[s0], n1 = g_norm_out[s1];
                    float n2 = g_norm_out[s2], n3 = g_norm_out[s3];
                    uint2 u0 = m1[s0 * 16 + lc4];
                    uint2 u1 = m1[s1 * 16 + lc4];
                    uint2 u2 = m1[s2 * 16 + lc4];
                    uint2 u3 = m1[s3 * 16 + lc4];
                    float2 p, q;
                    unpack_half4(u0, p, q);
                    a0.x = fmaf(p.x, n0, a0.x); a0.y = fmaf(p.y, n0, a0.y);
                    a0.z = fmaf(q.x, n0, a0.z); a0.w = fmaf(q.y, n0, a0.w);
                    unpack_half4(u1, p, q);
                    a1.x = fmaf(p.x, n1, a1.x); a1.y = fmaf(p.y, n1, a1.y);
                    a1.z = fmaf(q.x, n1, a1.z); a1.w = fmaf(q.y, n1, a1.w);
                    unpack_half4(u2, p, q);
                    a0.x = fmaf(p.x, n2, a0.x); a0.y = fmaf(p.y, n2, a0.y);
                    a0.z = fmaf(q.x, n2, a0.z); a0.w = fmaf(q.y, n2, a0.w);
                    unpack_half4(u3, p, q);
                    a1.x = fmaf(p.x, n3, a1.x); a1.y = fmaf(p.y, n3, a1.y);
                    a1.z = fmaf(q.x, n3, a1.z); a1.w = fmaf(q.y, n3, a1.w);
                }
                for (; e < end; e++) {
                    int s = g_csr_src[e];
                    float ns = g_norm_out[s];
                    float2 p, q;
                    unpack_half4(m1[s * 16 + lc4], p, q);
                    a0.x = fmaf(p.x, ns, a0.x); a0.y = fmaf(p.y, ns, a0.y);
                    a0.z = fmaf(q.x, ns, a0.z); a0.w = fmaf(q.y, ns, a0.w);
                }
                float ni = g_norm_in[row];
                float2 h0a, h0b;
                unpack_half4(reinterpret_cast<const uint2*>(g_h0h)[row * 16 + lc4], h0a, h0b);
                v.x = (h0a.x + (a0.x + a1.x) * ni + bv1.x) * sc;
                v.y = (h0a.y + (a0.y + a1.y) * ni + bv1.y) * sc;
                v.z = (h0b.x + (a0.z + a1.z) * ni + bv1.z) * sc;
                v.w = (h0b.y + (a0.w + a1.w) * ni + bv1.w) * sc;
                reinterpret_cast<uint2*>(g_h1h)[row * 16 + lc4] = pack_half4(v.x, v.y, v.z, v.w);
            }
            sHT[lc4 * 4 + ((0 + lc4) & 3)][r] = v.x;
            sHT[lc4 * 4 + ((1 + lc4) & 3)][r] = v.y;
            sHT[lc4 * 4 + ((2 + lc4) & 3)][r] = v.z;
            sHT[lc4 * 4 + ((3 + lc4) & 3)][r] = v.w;
        }
        __syncthreads();

        // gemm2: 4 rows x 4 cols per thread
        float4 acc[4];
        #pragma unroll
        for (int i = 0; i < 4; i++) acc[i] = make_float4(0.f, 0.f, 0.f, 0.f);
        #pragma unroll 4
        for (int c = 0; c < 16; c++) {
            #pragma unroll
            for (int j = 0; j < 4; j++) {
                int klog = c * 4 + j;
                int kp   = c * 4 + ((j + c) & 3);
                float4 wv = *(float4*)&sW[klog][j0];
                float4 a0 = *(float4*)&sHT[kp][r0];
                acc[0].x = fmaf(a0.x, wv.x, acc[0].x); acc[0].y = fmaf(a0.x, wv.y, acc[0].y);
                acc[0].z = fmaf(a0.x, wv.z, acc[0].z); acc[0].w = fmaf(a0.x, wv.w, acc[0].w);
                acc[1].x = fmaf(a0.y, wv.x, acc[1].x); acc[1].y = fmaf(a0.y, wv.y, acc[1].y);
                acc[1].z = fmaf(a0.y, wv.z, acc[1].z); acc[1].w = fmaf(a0.y, wv.w, acc[1].w);
                acc[2].x = fmaf(a0.z, wv.x, acc[2].x); acc[2].y = fmaf(a0.z, wv.y, acc[2].y);
                acc[2].z = fmaf(a0.z, wv.z, acc[2].z); acc[2].w = fmaf(a0.z, wv.w, acc[2].w);
                acc[3].x = fmaf(a0.w, wv.x, acc[3].x); acc[3].y = fmaf(a0.w, wv.y, acc[3].y);
                acc[3].z = fmaf(a0.w, wv.z, acc[3].z); acc[3].w = fmaf(a0.w, wv.w, acc[3].w);
            }
        }
        #pragma unroll
        for (int i = 0; i < 4; i++) {
            int row = br + r0 + i;
            if (row < n_nodes) {
                float ns = g_norm_out[row];
                reinterpret_cast<uint2*>(g_msg2)[row * 16 + tx] =
                    pack_half4(acc[i].x * ns, acc[i].y * ns, acc[i].z * ns, acc[i].w * ns);
            }
        }
    }

    // ---------------- device barrier #1 ----------------
    __threadfence();
    __syncthreads();
    if (tid == 0) {
        atomicAdd(&g_bar, 1u);
        while (atomicAdd(&g_bar, 0u) < gridDim.x) __nanosleep(64);
        __threadfence();
    }
    __syncthreads();

    // ---------------- phase 2: layer-2 aggregation + epilogue + BN stats ----------------
    __shared__ float ssum[64], ssq[64];
    if (tid < 64) { ssum[tid] = 0.f; ssq[tid] = 0.f; }
    __syncthreads();
    {
        int c = tid & 15;
        float4 bv = reinterpret_cast<const float4*>(b2)[c];
        float4 ls = make_float4(0.f, 0.f, 0.f, 0.f);
        float4 lq = make_float4(0.f, 0.f, 0.f, 0.f);
        const uint2* __restrict__ m2 = reinterpret_cast<const uint2*>(g_msg2);

        for (int node = blockIdx.x * 16 + (tid >> 4); node < n_nodes; node += gridDim.x * 16) {
            int beg = g_rowstart[node];
            int end = beg + g_deg_in[node];
            float4 a0 = make_float4(0.f, 0.f, 0.f, 0.f);
            float4 a1 = make_float4(0.f, 0.f, 0.f, 0.f);
            int e = beg;
            for (; e + 4 <= end; e += 4) {
                int s0 = g_csr_src[e], s1 = g_csr_src[e + 1];
                int s2 = g_csr_src[e + 2], s3 = g_csr_src[e + 3];
                uint2 u0 = m2[s0 * 16 + c];
                uint2 u1 = m2[s1 * 16 + c];
                uint2 u2 = m2[s2 * 16 + c];
                uint2 u3 = m2[s3 * 16 + c];
                float2 p, q;
                unpack_half4(u0, p, q);
                a0.x += p.x; a0.y += p.y; a0.z += q.x; a0.w += q.y;
                unpack_half4(u1, p, q);
                a1.x += p.x; a1.y += p.y; a1.z += q.x; a1.w += q.y;
                unpack_half4(u2, p, q);
                a0.x += p.x; a0.y += p.y; a0.z += q.x; a0.w += q.y;
                unpack_half4(u3, p, q);
                a1.x += p.x; a1.y += p.y; a1.z += q.x; a1.w += q.y;
            }
            for (; e < end; e++) {
                int s = g_csr_src[e];
                float2 p, q;
                unpack_half4(m2[s * 16 + c], p, q);
                a0.x += p.x; a0.y += p.y; a0.z += q.x; a0.w += q.y;
            }
            float ni = g_norm_in[node];
            float2 h1a, h1b;
            unpack_half4(reinterpret_cast<const uint2*>(g_h1h)[node * 16 + c], h1a, h1b);
            float4 h2;
            h2.x = (h1a.x + (a0.x + a1.x) * ni + bv.x) * sc;
            h2.y = (h1a.y + (a0.y + a1.y) * ni + bv.y) * sc;
            h2.z = (h1b.x + (a0.z + a1.z) * ni + bv.z) * sc;
            h2.w = (h1b.y + (a0.w + a1.w) * ni + bv.w) * sc;
            reinterpret_cast<float4*>(out)[node * 16 + c] = h2;
            ls.x += h2.x; ls.y += h2.y; ls.z += h2.z; ls.w += h2.w;
            lq.x += h2.x * h2.x; lq.y += h2.y * h2.y; lq.z += h2.z * h2.z; lq.w += h2.w * h2.w;
        }
        atomicAdd(&ssum[c * 4 + 0], ls.x); atomicAdd(&ssq[c * 4 + 0], lq.x);
        atomicAdd(&ssum[c * 4 + 1], ls.y); atomicAdd(&ssq[c * 4 + 1], lq.y);
        atomicAdd(&ssum[c * 4 + 2], ls.z); atomicAdd(&ssq[c * 4 + 2], lq.z);
        atomicAdd(&ssum[c * 4 + 3], ls.w); atomicAdd(&ssq[c * 4 + 3], lq.w);
    }
    __syncthreads();
    if (tid < 64) {
        atomicAdd(&g_stats[tid], ssum[tid]);
        atomicAdd(&g_stats[64 + tid], ssq[tid]);
    }

    // ---------------- device barrier #2 ----------------
    __threadfence();
    __syncthreads();
    if (tid == 0) {
        atomicAdd(&g_bar, 1u);
        while (atomicAdd(&g_bar, 0u) < 2u * gridDim.x) __nanosleep(64);
        __threadfence();
    }
    __syncthreads();

    // ---------------- phase 3: BN apply ----------------
    __shared__ float s_scale[64], s_shift[64];
    if (tid < 64) {
        int j = tid;
        volatile float* vs = g_stats;
        float inv_n = 1.f / (float)n_nodes;
        float mu = vs[j] * inv_n;
        float var = vs[64 + j] * inv_n - mu * mu;
        if (var < 0.f) var = 0.f;
        float g = rsqrtf(var + 1e-5f) * gamma[j];
        s_scale[j] = g;
        s_shift[j] = beta[j] - mu * g;
    }
    __syncthreads();
    int total4 = n_nodes * 16;
    int stride = gridDim.x * blockDim.x;
    for (int i = blockIdx.x * blockDim.x + tid; i < total4; i += stride) {
        float4 v = reinterpret_cast<float4*>(out)[i];
        int jj = (i & 15) << 2;
        v.x = v.x * s_scale[jj + 0] + s_shift[jj + 0];
        v.y = v.y * s_scale[jj + 1] + s_shift[jj + 1];
        v.z = v.z * s_scale[jj + 2] + s_shift[jj + 2];
        v.w = v.w * s_scale[jj + 3] + s_shift[jj + 3];
        reinterpret_cast<float4*>(out)[i] = v;
    }
}

// ---------------- launch ----------------
extern "C" void kernel_launch(void* const* d_in, const int* in_sizes, int n_in,
                              void* d_out, int out_size) {
    const int*   src   = (const int*)d_in[0];
    const int*   dst   = (const int*)d_in[1];
    const float* x     = (const float*)d_in[2];
    const float* fc_w  = (const float*)d_in[3];
    const float* fc_b  = (const float*)d_in[4];
    const float* w1    = (const float*)d_in[5];
    const float* b1    = (const float*)d_in[6];
    const float* w2    = (const float*)d_in[7];
    const float* b2    = (const float*)d_in[8];
    const float* gamma = (const float*)d_in[9];
    const float* beta  = (const float*)d_in[10];
    float* out = (float*)d_out;

    int n_edges = in_sizes[0];
    int n_nodes = in_sizes[2] / 128;

    static cudaStream_t s_build = nullptr;
    static cudaEvent_t ev_fork = nullptr, ev_join = nullptr;
    if (s_build == nullptr) {
        cudaStreamCreateWithFlags(&s_build, cudaStreamNonBlocking);
        cudaEventCreateWithFlags(&ev_fork, cudaEventDisableTiming);
        cudaEventCreateWithFlags(&ev_join, cudaEventDisableTiming);
    }

    cudaEventRecord(ev_fork, 0);
    cudaStreamWaitEvent(s_build, ev_fork, 0);
    zero_all_kernel<<<(n_nodes + 255) / 256, 256, 0, s_build>>>(n_nodes);
    degree_kernel<<<(n_edges + 255) / 256, 256, 0, s_build>>>(src, dst, n_edges);
    finalize_kernel<<<(n_nodes + 255) / 256, 256, 0, s_build>>>(n_nodes);
    bin_kernel<<<(n_edges + 255) / 256, 256, 0, s_build>>>(src, dst, n_edges);
    cudaEventRecord(ev_join, s_build);

    int gblocks = (n_nodes + 127) / 128;
    fcg1_kernel<<<gblocks, 256>>>(x, fc_w, fc_b, w1, n_nodes);

    cudaStreamWaitEvent(0, ev_join, 0);
    fused_tail_kernel<<<592, 256>>>(b1, w2, b2, gamma, beta, out, n_nodes);
}

// round 16
// speedup vs baseline: 1.1302x; 1.0082x over previous
#include <cuda_runtime.h>
#include <cuda_fp16.h>
#include <cstdint>

#define NMAX 100000
#define EMAX 800000
#define HID 64

// ---------------- scratch (device globals) ----------------
__device__ __half g_h0h[NMAX * HID];        // fc output (fp16)
__device__ __half g_h1h[NMAX * HID];        // layer-1 output (fp16)
__device__ __half g_msg1[NMAX * HID];       // layer-1 messages h0@w1 (UNscaled, fp16)
__device__ __half g_msg2[NMAX * HID];       // layer-2 messages (h1@w2)*norm_out (fp16)
__device__ int   g_deg_out[NMAX];
__device__ int   g_deg_in[NMAX];
__device__ int2  g_rowdeg[NMAX];            // {rowstart, deg_in} packed
__device__ float g_norm_out[NMAX];
__device__ float g_norm_in[NMAX];
__device__ int   g_cursor[NMAX];
__device__ int   g_csr_src[EMAX];
__device__ int   g_total;
__device__ unsigned int g_bar;
__device__ float g_stats[2 * HID];

__device__ __forceinline__ float scale_const() { return 0.70710678118654752440f; }

__device__ __forceinline__ uint2 pack_half4(float a, float b, float c, float d) {
    __half2 p0 = __floats2half2_rn(a, b);
    __half2 p1 = __floats2half2_rn(c, d);
    uint2 u;
    u.x = *reinterpret_cast<unsigned int*>(&p0);
    u.y = *reinterpret_cast<unsigned int*>(&p1);
    return u;
}
__device__ __forceinline__ void unpack_half4(uint2 u, float2& f0, float2& f1) {
    __half2 h0 = *reinterpret_cast<__half2*>(&u.x);
    __half2 h1 = *reinterpret_cast<__half2*>(&u.y);
    f0 = __half22float2(h0);
    f1 = __half22float2(h1);
}

// ---------------- graph build chain (side stream) ----------------
__global__ void zero_all_kernel(int n_nodes) {
    int idx = blockIdx.x * blockDim.x + threadIdx.x;
    if (idx < n_nodes) { g_deg_out[idx] = 0; g_deg_in[idx] = 0; }
    if (idx < 2 * HID) g_stats[idx] = 0.f;
    if (idx == 0) { g_total = 0; g_bar = 0u; }
}

__global__ void degree_kernel(const int* __restrict__ src, const int* __restrict__ dst, int n_edges) {
    int e = blockIdx.x * blockDim.x + threadIdx.x;
    if (e < n_edges) {
        atomicAdd(&g_deg_out[src[e]], 1);
        atomicAdd(&g_deg_in[dst[e]], 1);
    }
}

__global__ void finalize_kernel(int n_nodes) {
    int n = blockIdx.x * blockDim.x + threadIdx.x;
    if (n < n_nodes) {
        int deg = g_deg_in[n];
        int start = atomicAdd(&g_total, deg);
        g_rowdeg[n] = make_int2(start, deg);
        g_cursor[n] = start;
        int dov = g_deg_out[n]; if (dov < 1) dov = 1;
        int din = deg; if (din < 1) din = 1;
        g_norm_out[n] = rsqrtf((float)dov);
        g_norm_in[n]  = rsqrtf((float)din);
    }
}

__global__ void bin_kernel(const int* __restrict__ src, const int* __restrict__ dst, int n_edges) {
    int e = blockIdx.x * blockDim.x + threadIdx.x;
    if (e < n_edges) {
        int p = atomicAdd(&g_cursor[dst[e]], 1);
        g_csr_src[p] = src[e];
    }
}

// ======================================================================
// Fused fc + gemm1 (graph-independent), fp32 FMA, 128-row tiles:
//   h0 = x @ fc_w + fc_b   -> g_h0h (fp16)
//   msg1 = h0 @ w1         -> g_msg1 (fp16)
// ======================================================================
__global__ __launch_bounds__(256) void fcg1_kernel(const float* __restrict__ x,
                                                   const float* __restrict__ fcw,
                                                   const float* __restrict__ fcb,
                                                   const float* __restrict__ w1,
                                                   int n_nodes) {
    __shared__ float sXT[64][132];
    __shared__ float sW[64][64];
    int br = blockIdx.x * 128;
    int tid = threadIdx.x;
    int tx = tid & 15, ty = tid >> 4;
    int r0 = ty * 8, j0 = tx * 4;
    int lc4 = tid & 15, lr0 = tid >> 4;

    float4 acc[8];
    #pragma unroll
    for (int i = 0; i < 8; i++) acc[i] = make_float4(0.f, 0.f, 0.f, 0.f);

    for (int kc = 0; kc < 2; kc++) {
        if (kc) __syncthreads();
        for (int i = tid; i < 1024; i += 256) {
            int k = i >> 4, c = (i & 15) << 2;
            *(float4*)&sW[k][c] = *(const float4*)&fcw[(kc * 64 + k) * 64 + c];
        }
        #pragma unroll
        for (int t = 0; t < 8; t++) {
            int r = lr0 + t * 16;
            int row = br + r;
            float4 v = make_float4(0.f, 0.f, 0.f, 0.f);
            if (row < n_nodes) v = *(const float4*)&x[row * 128 + kc * 64 + (lc4 << 2)];
            sXT[lc4 * 4 + ((0 + lc4) & 3)][r] = v.x;
            sXT[lc4 * 4 + ((1 + lc4) & 3)][r] = v.y;
            sXT[lc4 * 4 + ((2 + lc4) & 3)][r] = v.z;
            sXT[lc4 * 4 + ((3 + lc4) & 3)][r] = v.w;
        }
        __syncthreads();
        #pragma unroll 4
        for (int c = 0; c < 16; c++) {
            #pragma unroll
            for (int j = 0; j < 4; j++) {
                int klog = c * 4 + j;
                int kp   = c * 4 + ((j + c) & 3);
                float4 wv = *(float4*)&sW[klog][j0];
                float4 a0 = *(float4*)&sXT[kp][r0];
                float4 a1 = *(float4*)&sXT[kp][r0 + 4];
                acc[0].x = fmaf(a0.x, wv.x, acc[0].x); acc[0].y = fmaf(a0.x, wv.y, acc[0].y);
                acc[0].z = fmaf(a0.x, wv.z, acc[0].z); acc[0].w = fmaf(a0.x, wv.w, acc[0].w);
                acc[1].x = fmaf(a0.y, wv.x, acc[1].x); acc[1].y = fmaf(a0.y, wv.y, acc[1].y);
                acc[1].z = fmaf(a0.y, wv.z, acc[1].z); acc[1].w = fmaf(a0.y, wv.w, acc[1].w);
                acc[2].x = fmaf(a0.z, wv.x, acc[2].x); acc[2].y = fmaf(a0.z, wv.y, acc[2].y);
                acc[2].z = fmaf(a0.z, wv.z, acc[2].z); acc[2].w = fmaf(a0.z, wv.w, acc[2].w);
                acc[3].x = fmaf(a0.w, wv.x, acc[3].x); acc[3].y = fmaf(a0.w, wv.y, acc[3].y);
                acc[3].z = fmaf(a0.w, wv.z, acc[3].z); acc[3].w = fmaf(a0.w, wv.w, acc[3].w);
                acc[4].x = fmaf(a1.x, wv.x, acc[4].x); acc[4].y = fmaf(a1.x, wv.y, acc[4].y);
                acc[4].z = fmaf(a1.x, wv.z, acc[4].z); acc[4].w = fmaf(a1.x, wv.w, acc[4].w);
                acc[5].x = fmaf(a1.y, wv.x, acc[5].x); acc[5].y = fmaf(a1.y, wv.y, acc[5].y);
                acc[5].z = fmaf(a1.y, wv.z, acc[5].z); acc[5].w = fmaf(a1.y, wv.w, acc[5].w);
                acc[6].x = fmaf(a1.z, wv.x, acc[6].x); acc[6].y = fmaf(a1.z, wv.y, acc[6].y);
                acc[6].z = fmaf(a1.z, wv.z, acc[6].z); acc[6].w = fmaf(a1.z, wv.w, acc[6].w);
                acc[7].x = fmaf(a1.w, wv.x, acc[7].x); acc[7].y = fmaf(a1.w, wv.y, acc[7].y);
                acc[7].z = fmaf(a1.w, wv.z, acc[7].z); acc[7].w = fmaf(a1.w, wv.w, acc[7].w);
            }
        }
    }

    __syncthreads();
    {
        float4 bv = *(const float4*)&fcb[j0];
        #pragma unroll
        for (int i = 0; i < 8; i++) {
            int row = br + r0 + i;
            float4 o;
            o.x = acc[i].x + bv.x; o.y = acc[i].y + bv.y;
            o.z = acc[i].z + bv.z; o.w = acc[i].w + bv.w;
            if (row < n_nodes)
                reinterpret_cast<uint2*>(g_h0h)[row * 16 + tx] = pack_half4(o.x, o.y, o.z, o.w);
            else { o = make_float4(0.f, 0.f, 0.f, 0.f); }
            sXT[tx * 4 + ((0 + tx) & 3)][r0 + i] = o.x;
            sXT[tx * 4 + ((1 + tx) & 3)][r0 + i] = o.y;
            sXT[tx * 4 + ((2 + tx) & 3)][r0 + i] = o.z;
            sXT[tx * 4 + ((3 + tx) & 3)][r0 + i] = o.w;
        }
    }
    for (int i = tid; i < 1024; i += 256) {
        int k = i >> 4, c = (i & 15) << 2;
        *(float4*)&sW[k][c] = *(const float4*)&w1[k * 64 + c];
    }
    __syncthreads();

    #pragma unroll
    for (int i = 0; i < 8; i++) acc[i] = make_float4(0.f, 0.f, 0.f, 0.f);
    #pragma unroll 4
    for (int c = 0; c < 16; c++) {
        #pragma unroll
        for (int j = 0; j < 4; j++) {
            int klog = c * 4 + j;
            int kp   = c * 4 + ((j + c) & 3);
            float4 wv = *(float4*)&sW[klog][j0];
            float4 a0 = *(float4*)&sXT[kp][r0];
            float4 a1 = *(float4*)&sXT[kp][r0 + 4];
            acc[0].x = fmaf(a0.x, wv.x, acc[0].x); acc[0].y = fmaf(a0.x, wv.y, acc[0].y);
            acc[0].z = fmaf(a0.x, wv.z, acc[0].z); acc[0].w = fmaf(a0.x, wv.w, acc[0].w);
            acc[1].x = fmaf(a0.y, wv.x, acc[1].x); acc[1].y = fmaf(a0.y, wv.y, acc[1].y);
            acc[1].z = fmaf(a0.y, wv.z, acc[1].z); acc[1].w = fmaf(a0.y, wv.w, acc[1].w);
            acc[2].x = fmaf(a0.z, wv.x, acc[2].x); acc[2].y = fmaf(a0.z, wv.y, acc[2].y);
            acc[2].z = fmaf(a0.z, wv.z, acc[2].z); acc[2].w = fmaf(a0.z, wv.w, acc[2].w);
            acc[3].x = fmaf(a0.w, wv.x, acc[3].x); acc[3].y = fmaf(a0.w, wv.y, acc[3].y);
            acc[3].z = fmaf(a0.w, wv.z, acc[3].z); acc[3].w = fmaf(a0.w, wv.w, acc[3].w);
            acc[4].x = fmaf(a1.x, wv.x, acc[4].x); acc[4].y = fmaf(a1.x, wv.y, acc[4].y);
            acc[4].z = fmaf(a1.x, wv.z, acc[4].z); acc[4].w = fmaf(a1.x, wv.w, acc[4].w);
            acc[5].x = fmaf(a1.y, wv.x, acc[5].x); acc[5].y = fmaf(a1.y, wv.y, acc[5].y);
            acc[5].z = fmaf(a1.y, wv.z, acc[5].z); acc[5].w = fmaf(a1.y, wv.w, acc[5].w);
            acc[6].x = fmaf(a1.z, wv.x, acc[6].x); acc[6].y = fmaf(a1.z, wv.y, acc[6].y);
            acc[6].z = fmaf(a1.z, wv.z, acc[6].z); acc[6].w = fmaf(a1.z, wv.w, acc[6].w);
            acc[7].x = fmaf(a1.w, wv.x, acc[7].x); acc[7].y = fmaf(a1.w, wv.y, acc[7].y);
            acc[7].z = fmaf(a1.w, wv.z, acc[7].z); acc[7].w = fmaf(a1.w, wv.w, acc[7].w);
        }
    }
    #pragma unroll
    for (int i = 0; i < 8; i++) {
        int row = br + r0 + i;
        if (row < n_nodes)
            reinterpret_cast<uint2*>(g_msg1)[row * 16 + tx] =
                pack_half4(acc[i].x, acc[i].y, acc[i].z, acc[i].w);
    }
}

// ======================================================================
// Persistent kernel (grid MUST be 592 = 148 SMs x 4 blocks, single wave):
//  phase 1: grid-stride 64-row tiles: CSR gather (msg1) + layer-1 epilogue
//           -> g_h1h, then gemm2 -> g_msg2 (pre-scaled by norm_out)
//  [device barrier]
//  phase 2: layer-2 aggregation + epilogue -> out, BN statistics
//  [device barrier]
//  phase 3: BN apply on out
// ======================================================================
__global__ __launch_bounds__(256, 4) void fused_tail_kernel(const float* __restrict__ b1,
                                                            const float* __restrict__ w2,
                                                            const float* __restrict__ b2,
                                                            const float* __restrict__ gamma,
                                                            const float* __restrict__ beta,
                                                            float* __restrict__ out,
                                                            int n_nodes) {
    __shared__ float sHT[64][68];
    __shared__ float sW[64][64];
    __shared__ float sNO[64];    // per-tile norm_out for msg2 epilogue
    int tid = threadIdx.x;
    int tx = tid & 15, ty = tid >> 4;
    int r0 = ty * 4, j0 = tx * 4;
    int lc4 = tid & 15, lr0 = tid >> 4;
    const float sc = scale_const();
    const uint2* __restrict__ m1 = reinterpret_cast<const uint2*>(g_msg1);

    // w2 into smem once (sW untouched across tiles)
    for (int i = tid; i < 1024; i += 256) {
        int k = i >> 4, c = (i & 15) << 2;
        *(float4*)&sW[k][c] = *(const float4*)&w2[k * 64 + c];
    }

    // ---------------- phase 1: gather + gemm2 over 64-row tiles ----------------
    int ntiles = (n_nodes + 63) / 64;
    float4 bv1 = *(const float4*)&b1[lc4 << 2];
    for (int tile = blockIdx.x; tile < ntiles; tile += gridDim.x) {
        int br = tile * 64;
        __syncthreads();   // previous tile's gemm reads done before refill
        // hoisted norm_out for this tile (first 64 threads)
        if (tid < 64) {
            int row = br + tid;
            sNO[tid] = (row < n_nodes) ? g_norm_out[row] : 0.f;
        }
        #pragma unroll
        for (int t = 0; t < 4; t++) {
            int r = lr0 + t * 16;
            int row = br + r;
            float4 v = make_float4(0.f, 0.f, 0.f, 0.f);
            if (row < n_nodes) {
                int2 rd = g_rowdeg[row];
                int beg = rd.x, end = rd.x + rd.y;
                float4 a0 = make_float4(0.f, 0.f, 0.f, 0.f);
                float4 a1 = make_float4(0.f, 0.f, 0.f, 0.f);
                int e = beg;
                for (; e + 4 <= end; e += 4) {
                    int s0 = g_csr_src[e], s1 = g_csr_src[e + 1];
                    int s2 = g_csr_src[e + 2], s3 = g_csr_src[e + 3];
                    float n0 = g_norm_out[s0], n1 = g_norm_out[s1];
                    float n2 = g_norm_out[s2], n3 = g_norm_out[s3];
                    uint2 u0 = m1[s0 * 16 + lc4];
                    uint2 u1 = m1[s1 * 16 + lc4];
                    uint2 u2 = m1[s2 * 16 + lc4];
                    uint2 u3 = m1[s3 * 16 + lc4];
                    float2 p, q;
                    unpack_half4(u0, p, q);
                    a0.x = fmaf(p.x, n0, a0.x); a0.y = fmaf(p.y, n0, a0.y);
                    a0.z = fmaf(q.x, n0, a0.z); a0.w = fmaf(q.y, n0, a0.w);
                    unpack_half4(u1, p, q);
                    a1.x = fmaf(p.x, n1, a1.x); a1.y = fmaf(p.y, n1, a1.y);
                    a1.z = fmaf(q.x, n1, a1.z); a1.w = fmaf(q.y, n1, a1.w);
                    unpack_half4(u2, p, q);
                    a0.x = fmaf(p.x, n2, a0.x); a0.y = fmaf(p.y, n2, a0.y);
                    a0.z = fmaf(q.x, n2, a0.z); a0.w = fmaf(q.y, n2, a0.w);
                    unpack_half4(u3, p, q);
                    a1.x = fmaf(p.x, n3, a1.x); a1.y = fmaf(p.y, n3, a1.y);
                    a1.z = fmaf(q.x, n3, a1.z); a1.w = fmaf(q.y, n3, a1.w);
                }
                for (; e < end; e++) {
                    int s = g_csr_src[e];
                    float ns = g_norm_out[s];
                    float2 p, q;
                    unpack_half4(m1[s * 16 + lc4], p, q);
                    a0.x = fmaf(p.x, ns, a0.x); a0.y = fmaf(p.y, ns, a0.y);
                    a0.z = fmaf(q.x, ns, a0.z); a0.w = fmaf(q.y, ns, a0.w);
                }
                float ni = g_norm_in[row];
                float2 h0a, h0b;
                unpack_half4(reinterpret_cast<const uint2*>(g_h0h)[row * 16 + lc4], h0a, h0b);
                v.x = (h0a.x + (a0.x + a1.x) * ni + bv1.x) * sc;
                v.y = (h0a.y + (a0.y + a1.y) * ni + bv1.y) * sc;
                v.z = (h0b.x + (a0.z + a1.z) * ni + bv1.z) * sc;
                v.w = (h0b.y + (a0.w + a1.w) * ni + bv1.w) * sc;
                reinterpret_cast<uint2*>(g_h1h)[row * 16 + lc4] = pack_half4(v.x, v.y, v.z, v.w);
            }
            sHT[lc4 * 4 + ((0 + lc4) & 3)][r] = v.x;
            sHT[lc4 * 4 + ((1 + lc4) & 3)][r] = v.y;
            sHT[lc4 * 4 + ((2 + lc4) & 3)][r] = v.z;
            sHT[lc4 * 4 + ((3 + lc4) & 3)][r] = v.w;
        }
        __syncthreads();

        // gemm2: 4 rows x 4 cols per thread
        float4 acc[4];
        #pragma unroll
        for (int i = 0; i < 4; i++) acc[i] = make_float4(0.f, 0.f, 0.f, 0.f);
        #pragma unroll 4
        for (int c = 0; c < 16; c++) {
            #pragma unroll
            for (int j = 0; j < 4; j++) {
                int klog = c * 4 + j;
                int kp   = c * 4 + ((j + c) & 3);
                float4 wv = *(float4*)&sW[klog][j0];
                float4 a0 = *(float4*)&sHT[kp][r0];
                acc[0].x = fmaf(a0.x, wv.x, acc[0].x); acc[0].y = fmaf(a0.x, wv.y, acc[0].y);
                acc[0].z = fmaf(a0.x, wv.z, acc[0].z); acc[0].w = fmaf(a0.x, wv.w, acc[0].w);
                acc[1].x = fmaf(a0.y, wv.x, acc[1].x); acc[1].y = fmaf(a0.y, wv.y, acc[1].y);
                acc[1].z = fmaf(a0.y, wv.z, acc[1].z); acc[1].w = fmaf(a0.y, wv.w, acc[1].w);
                acc[2].x = fmaf(a0.z, wv.x, acc[2].x); acc[2].y = fmaf(a0.z, wv.y, acc[2].y);
                acc[2].z = fmaf(a0.z, wv.z, acc[2].z); acc[2].w = fmaf(a0.z, wv.w, acc[2].w);
                acc[3].x = fmaf(a0.w, wv.x, acc[3].x); acc[3].y = fmaf(a0.w, wv.y, acc[3].y);
                acc[3].z = fmaf(a0.w, wv.z, acc[3].z); acc[3].w = fmaf(a0.w, wv.w, acc[3].w);
            }
        }
        #pragma unroll
        for (int i = 0; i < 4; i++) {
            int row = br + r0 + i;
            if (row < n_nodes) {
                float ns = sNO[r0 + i];
                reinterpret_cast<uint2*>(g_msg2)[row * 16 + tx] =
                    pack_half4(acc[i].x * ns, acc[i].y * ns, acc[i].z * ns, acc[i].w * ns);
            }
        }
    }

    // ---------------- device barrier #1 ----------------
    __threadfence();
    __syncthreads();
    if (tid == 0) {
        atomicAdd(&g_bar, 1u);
        while (atomicAdd(&g_bar, 0u) < gridDim.x) __nanosleep(64);
        __threadfence();
    }
    __syncthreads();

    // ---------------- phase 2: layer-2 aggregation + epilogue + BN stats ----------------
    __shared__ float ssum[64], ssq[64];
    if (tid < 64) { ssum[tid] = 0.f; ssq[tid] = 0.f; }
    __syncthreads();
    {
        int c = tid & 15;
        float4 bv = reinterpret_cast<const float4*>(b2)[c];
        float4 ls = make_float4(0.f, 0.f, 0.f, 0.f);
        float4 lq = make_float4(0.f, 0.f, 0.f, 0.f);
        const uint2* __restrict__ m2 = reinterpret_cast<const uint2*>(g_msg2);

        for (int node = blockIdx.x * 16 + (tid >> 4); node < n_nodes; node += gridDim.x * 16) {
            int2 rd = g_rowdeg[node];
            int beg = rd.x, end = rd.x + rd.y;
            float4 a0 = make_float4(0.f, 0.f, 0.f, 0.f);
            float4 a1 = make_float4(0.f, 0.f, 0.f, 0.f);
            int e = beg;
            for (; e + 4 <= end; e += 4) {
                int s0 = g_csr_src[e], s1 = g_csr_src[e + 1];
                int s2 = g_csr_src[e + 2], s3 = g_csr_src[e + 3];
                uint2 u0 = m2[s0 * 16 + c];
                uint2 u1 = m2[s1 * 16 + c];
                uint2 u2 = m2[s2 * 16 + c];
                uint2 u3 = m2[s3 * 16 + c];
                float2 p, q;
                unpack_half4(u0, p, q);
                a0.x += p.x; a0.y += p.y; a0.z += q.x; a0.w += q.y;
                unpack_half4(u1, p, q);
                a1.x += p.x; a1.y += p.y; a1.z += q.x; a1.w += q.y;
                unpack_half4(u2, p, q);
                a0.x += p.x; a0.y += p.y; a0.z += q.x; a0.w += q.y;
                unpack_half4(u3, p, q);
                a1.x += p.x; a1.y += p.y; a1.z += q.x; a1.w += q.y;
            }
            for (; e < end; e++) {
                int s = g_csr_src[e];
                float2 p, q;
                unpack_half4(m2[s * 16 + c], p, q);
                a0.x += p.x; a0.y += p.y; a0.z += q.x; a0.w += q.y;
            }
            float ni = g_norm_in[node];
            float2 h1a, h1b;
            unpack_half4(reinterpret_cast<const uint2*>(g_h1h)[node * 16 + c], h1a, h1b);
            float4 h2;
            h2.x = (h1a.x + (a0.x + a1.x) * ni + bv.x) * sc;
            h2.y = (h1a.y + (a0.y + a1.y) * ni + bv.y) * sc;
            h2.z = (h1b.x + (a0.z + a1.z) * ni + bv.z) * sc;
            h2.w = (h1b.y + (a0.w + a1.w) * ni + bv.w) * sc;
            reinterpret_cast<float4*>(out)[node * 16 + c] = h2;
            ls.x += h2.x; ls.y += h2.y; ls.z += h2.z; ls.w += h2.w;
            lq.x += h2.x * h2.x; lq.y += h2.y * h2.y; lq.z += h2.z * h2.z; lq.w += h2.w * h2.w;
        }
        atomicAdd(&ssum[c * 4 + 0], ls.x); atomicAdd(&ssq[c * 4 + 0], lq.x);
        atomicAdd(&ssum[c * 4 + 1], ls.y); atomicAdd(&ssq[c * 4 + 1], lq.y);
        atomicAdd(&ssum[c * 4 + 2], ls.z); atomicAdd(&ssq[c * 4 + 2], lq.z);
        atomicAdd(&ssum[c * 4 + 3], ls.w); atomicAdd(&ssq[c * 4 + 3], lq.w);
    }
    __syncthreads();
    if (tid < 64) {
        atomicAdd(&g_stats[tid], ssum[tid]);
        atomicAdd(&g_stats[64 + tid], ssq[tid]);
    }

    // ---------------- device barrier #2 ----------------
    __threadfence();
    __syncthreads();
    if (tid == 0) {
        atomicAdd(&g_bar, 1u);
        while (atomicAdd(&g_bar, 0u) < 2u * gridDim.x) __nanosleep(64);
        __threadfence();
    }
    __syncthreads();

    // ---------------- phase 3: BN apply ----------------
    __shared__ float s_scale[64], s_shift[64];
    if (tid < 64) {
        int j = tid;
        volatile float* vs = g_stats;
        float inv_n = 1.f / (float)n_nodes;
        float mu = vs[j] * inv_n;
        float var = vs[64 + j] * inv_n - mu * mu;
        if (var < 0.f) var = 0.f;
        float g = rsqrtf(var + 1e-5f) * gamma[j];
        s_scale[j] = g;
        s_shift[j] = beta[j] - mu * g;
    }
    __syncthreads();
    int total4 = n_nodes * 16;
    int stride = gridDim.x * blockDim.x;
    for (int i = blockIdx.x * blockDim.x + tid; i < total4; i += stride) {
        float4 v = reinterpret_cast<float4*>(out)[i];
        int jj = (i & 15) << 2;
        v.x = v.x * s_scale[jj + 0] + s_shift[jj + 0];
        v.y = v.y * s_scale[jj + 1] + s_shift[jj + 1];
        v.z = v.z * s_scale[jj + 2] + s_shift[jj + 2];
        v.w = v.w * s_scale[jj + 3] + s_shift[jj + 3];
        reinterpret_cast<float4*>(out)[i] = v;
    }
}

// ---------------- launch ----------------
extern "C" void kernel_launch(void* const* d_in, const int* in_sizes, int n_in,
                              void* d_out, int out_size) {
    const int*   src   = (const int*)d_in[0];
    const int*   dst   = (const int*)d_in[1];
    const float* x     = (const float*)d_in[2];
    const float* fc_w  = (const float*)d_in[3];
    const float* fc_b  = (const float*)d_in[4];
    const float* w1    = (const float*)d_in[5];
    const float* b1    = (const float*)d_in[6];
    const float* w2    = (const float*)d_in[7];
    const float* b2    = (const float*)d_in[8];
    const float* gamma = (const float*)d_in[9];
    const float* beta  = (const float*)d_in[10];
    float* out = (float*)d_out;

    int n_edges = in_sizes[0];
    int n_nodes = in_sizes[2] / 128;

    static cudaStream_t s_build = nullptr;
    static cudaEvent_t ev_fork = nullptr, ev_join = nullptr;
    if (s_build == nullptr) {
        cudaStreamCreateWithFlags(&s_build, cudaStreamNonBlocking);
        cudaEventCreateWithFlags(&ev_fork, cudaEventDisableTiming);
        cudaEventCreateWithFlags(&ev_join, cudaEventDisableTiming);
    }

    cudaEventRecord(ev_fork, 0);
    cudaStreamWaitEvent(s_build, ev_fork, 0);
    zero_all_kernel<<<(n_nodes + 255) / 256, 256, 0, s_build>>>(n_nodes);
    degree_kernel<<<(n_edges + 255) / 256, 256, 0, s_build>>>(src, dst, n_edges);
    finalize_kernel<<<(n_nodes + 255) / 256, 256, 0, s_build>>>(n_nodes);
    bin_kernel<<<(n_edges + 255) / 256, 256, 0, s_build>>>(src, dst, n_edges);
    cudaEventRecord(ev_join, s_build);

    int gblocks = (n_nodes + 127) / 128;
    fcg1_kernel<<<gblocks, 256>>>(x, fc_w, fc_b, w1, n_nodes);

    cudaStreamWaitEvent(0, ev_join, 0);
    fused_tail_kernel<<<592, 256>>>(b1, w2, b2, gamma, beta, out, n_nodes);
}

// round 17
// speedup vs baseline: 1.1350x; 1.0042x over previous
#include <cuda_runtime.h>
#include <cuda_fp16.h>
#include <cstdint>

#define NMAX 100000
#define EMAX 800000
#define HID 64

// ---------------- scratch (device globals) ----------------
__device__ __half g_h0h[NMAX * HID];        // fc output (fp16)
__device__ __half g_h1h[NMAX * HID];        // layer-1 output (fp16)
__device__ __half g_msg1[NMAX * HID];       // layer-1 messages; REUSED as pre-BN h2 (fp16) in phase 2
__device__ __half g_msg2[NMAX * HID];       // layer-2 messages (h1@w2)*norm_out (fp16)
__device__ int   g_deg_out[NMAX];
__device__ int   g_deg_in[NMAX];
__device__ int2  g_rowdeg[NMAX];            // {rowstart, deg_in} packed
__device__ float g_norm_out[NMAX];
__device__ float g_norm_in[NMAX];
__device__ int   g_cursor[NMAX];
__device__ int   g_csr_src[EMAX];
__device__ int   g_total;
__device__ unsigned int g_bar;
__device__ float g_stats[2 * HID];

__device__ __forceinline__ float scale_const() { return 0.70710678118654752440f; }

__device__ __forceinline__ uint2 pack_half4(float a, float b, float c, float d) {
    __half2 p0 = __floats2half2_rn(a, b);
    __half2 p1 = __floats2half2_rn(c, d);
    uint2 u;
    u.x = *reinterpret_cast<unsigned int*>(&p0);
    u.y = *reinterpret_cast<unsigned int*>(&p1);
    return u;
}
__device__ __forceinline__ void unpack_half4(uint2 u, float2& f0, float2& f1) {
    __half2 h0 = *reinterpret_cast<__half2*>(&u.x);
    __half2 h1 = *reinterpret_cast<__half2*>(&u.y);
    f0 = __half22float2(h0);
    f1 = __half22float2(h1);
}

// ---------------- graph build chain (side stream) ----------------
__global__ void zero_all_kernel(int n_nodes) {
    int idx = blockIdx.x * blockDim.x + threadIdx.x;
    if (idx < n_nodes) { g_deg_out[idx] = 0; g_deg_in[idx] = 0; }
    if (idx < 2 * HID) g_stats[idx] = 0.f;
    if (idx == 0) { g_total = 0; g_bar = 0u; }
}

__global__ void degree_kernel(const int* __restrict__ src, const int* __restrict__ dst, int n_edges) {
    int e = blockIdx.x * blockDim.x + threadIdx.x;
    if (e < n_edges) {
        atomicAdd(&g_deg_out[src[e]], 1);
        atomicAdd(&g_deg_in[dst[e]], 1);
    }
}

__global__ void finalize_kernel(int n_nodes) {
    int n = blockIdx.x * blockDim.x + threadIdx.x;
    if (n < n_nodes) {
        int deg = g_deg_in[n];
        int start = atomicAdd(&g_total, deg);
        g_rowdeg[n] = make_int2(start, deg);
        g_cursor[n] = start;
        int dov = g_deg_out[n]; if (dov < 1) dov = 1;
        int din = deg; if (din < 1) din = 1;
        g_norm_out[n] = rsqrtf((float)dov);
        g_norm_in[n]  = rsqrtf((float)din);
    }
}

__global__ void bin_kernel(const int* __restrict__ src, const int* __restrict__ dst, int n_edges) {
    int e = blockIdx.x * blockDim.x + threadIdx.x;
    if (e < n_edges) {
        int p = atomicAdd(&g_cursor[dst[e]], 1);
        g_csr_src[p] = src[e];
    }
}

// ======================================================================
// Fused fc + gemm1 (graph-independent), fp32 FMA, 128-row tiles:
//   h0 = x @ fc_w + fc_b   -> g_h0h (fp16)
//   msg1 = h0 @ w1         -> g_msg1 (fp16)
// ======================================================================
__global__ __launch_bounds__(256) void fcg1_kernel(const float* __restrict__ x,
                                                   const float* __restrict__ fcw,
                                                   const float* __restrict__ fcb,
                                                   const float* __restrict__ w1,
                                                   int n_nodes) {
    __shared__ float sXT[64][132];
    __shared__ float sW[64][64];
    int br = blockIdx.x * 128;
    int tid = threadIdx.x;
    int tx = tid & 15, ty = tid >> 4;
    int r0 = ty * 8, j0 = tx * 4;
    int lc4 = tid & 15, lr0 = tid >> 4;

    float4 acc[8];
    #pragma unroll
    for (int i = 0; i < 8; i++) acc[i] = make_float4(0.f, 0.f, 0.f, 0.f);

    for (int kc = 0; kc < 2; kc++) {
        if (kc) __syncthreads();
        for (int i = tid; i < 1024; i += 256) {
            int k = i >> 4, c = (i & 15) << 2;
            *(float4*)&sW[k][c] = *(const float4*)&fcw[(kc * 64 + k) * 64 + c];
        }
        #pragma unroll
        for (int t = 0; t < 8; t++) {
            int r = lr0 + t * 16;
            int row = br + r;
            float4 v = make_float4(0.f, 0.f, 0.f, 0.f);
            if (row < n_nodes) v = *(const float4*)&x[row * 128 + kc * 64 + (lc4 << 2)];
            sXT[lc4 * 4 + ((0 + lc4) & 3)][r] = v.x;
            sXT[lc4 * 4 + ((1 + lc4) & 3)][r] = v.y;
            sXT[lc4 * 4 + ((2 + lc4) & 3)][r] = v.z;
            sXT[lc4 * 4 + ((3 + lc4) & 3)][r] = v.w;
        }
        __syncthreads();
        #pragma unroll 4
        for (int c = 0; c < 16; c++) {
            #pragma unroll
            for (int j = 0; j < 4; j++) {
                int klog = c * 4 + j;
                int kp   = c * 4 + ((j + c) & 3);
                float4 wv = *(float4*)&sW[klog][j0];
                float4 a0 = *(float4*)&sXT[kp][r0];
                float4 a1 = *(float4*)&sXT[kp][r0 + 4];
                acc[0].x = fmaf(a0.x, wv.x, acc[0].x); acc[0].y = fmaf(a0.x, wv.y, acc[0].y);
                acc[0].z = fmaf(a0.x, wv.z, acc[0].z); acc[0].w = fmaf(a0.x, wv.w, acc[0].w);
                acc[1].x = fmaf(a0.y, wv.x, acc[1].x); acc[1].y = fmaf(a0.y, wv.y, acc[1].y);
                acc[1].z = fmaf(a0.y, wv.z, acc[1].z); acc[1].w = fmaf(a0.y, wv.w, acc[1].w);
                acc[2].x = fmaf(a0.z, wv.x, acc[2].x); acc[2].y = fmaf(a0.z, wv.y, acc[2].y);
                acc[2].z = fmaf(a0.z, wv.z, acc[2].z); acc[2].w = fmaf(a0.z, wv.w, acc[2].w);
                acc[3].x = fmaf(a0.w, wv.x, acc[3].x); acc[3].y = fmaf(a0.w, wv.y, acc[3].y);
                acc[3].z = fmaf(a0.w, wv.z, acc[3].z); acc[3].w = fmaf(a0.w, wv.w, acc[3].w);
                acc[4].x = fmaf(a1.x, wv.x, acc[4].x); acc[4].y = fmaf(a1.x, wv.y, acc[4].y);
                acc[4].z = fmaf(a1.x, wv.z, acc[4].z); acc[4].w = fmaf(a1.x, wv.w, acc[4].w);
                acc[5].x = fmaf(a1.y, wv.x, acc[5].x); acc[5].y = fmaf(a1.y, wv.y, acc[5].y);
                acc[5].z = fmaf(a1.y, wv.z, acc[5].z); acc[5].w = fmaf(a1.y, wv.w, acc[5].w);
                acc[6].x = fmaf(a1.z, wv.x, acc[6].x); acc[6].y = fmaf(a1.z, wv.y, acc[6].y);
                acc[6].z = fmaf(a1.z, wv.z, acc[6].z); acc[6].w = fmaf(a1.z, wv.w, acc[6].w);
                acc[7].x = fmaf(a1.w, wv.x, acc[7].x); acc[7].y = fmaf(a1.w, wv.y, acc[7].y);
                acc[7].z = fmaf(a1.w, wv.z, acc[7].z); acc[7].w = fmaf(a1.w, wv.w, acc[7].w);
            }
        }
    }

    __syncthreads();
    {
        float4 bv = *(const float4*)&fcb[j0];
        #pragma unroll
        for (int i = 0; i < 8; i++) {
            int row = br + r0 + i;
            float4 o;
            o.x = acc[i].x + bv.x; o.y = acc[i].y + bv.y;
            o.z = acc[i].z + bv.z; o.w = acc[i].w + bv.w;
            if (row < n_nodes)
                reinterpret_cast<uint2*>(g_h0h)[row * 16 + tx] = pack_half4(o.x, o.y, o.z, o.w);
            else { o = make_float4(0.f, 0.f, 0.f, 0.f); }
            sXT[tx * 4 + ((0 + tx) & 3)][r0 + i] = o.x;
            sXT[tx * 4 + ((1 + tx) & 3)][r0 + i] = o.y;
            sXT[tx * 4 + ((2 + tx) & 3)][r0 + i] = o.z;
            sXT[tx * 4 + ((3 + tx) & 3)][r0 + i] = o.w;
        }
    }
    for (int i = tid; i < 1024; i += 256) {
        int k = i >> 4, c = (i & 15) << 2;
        *(float4*)&sW[k][c] = *(const float4*)&w1[k * 64 + c];
    }
    __syncthreads();

    #pragma unroll
    for (int i = 0; i < 8; i++) acc[i] = make_float4(0.f, 0.f, 0.f, 0.f);
    #pragma unroll 4
    for (int c = 0; c < 16; c++) {
        #pragma unroll
        for (int j = 0; j < 4; j++) {
            int klog = c * 4 + j;
            int kp   = c * 4 + ((j + c) & 3);
            float4 wv = *(float4*)&sW[klog][j0];
            float4 a0 = *(float4*)&sXT[kp][r0];
            float4 a1 = *(float4*)&sXT[kp][r0 + 4];
            acc[0].x = fmaf(a0.x, wv.x, acc[0].x); acc[0].y = fmaf(a0.x, wv.y, acc[0].y);
            acc[0].z = fmaf(a0.x, wv.z, acc[0].z); acc[0].w = fmaf(a0.x, wv.w, acc[0].w);
            acc[1].x = fmaf(a0.y, wv.x, acc[1].x); acc[1].y = fmaf(a0.y, wv.y, acc[1].y);
            acc[1].z = fmaf(a0.y, wv.z, acc[1].z); acc[1].w = fmaf(a0.y, wv.w, acc[1].w);
            acc[2].x = fmaf(a0.z, wv.x, acc[2].x); acc[2].y = fmaf(a0.z, wv.y, acc[2].y);
            acc[2].z = fmaf(a0.z, wv.z, acc[2].z); acc[2].w = fmaf(a0.z, wv.w, acc[2].w);
            acc[3].x = fmaf(a0.w, wv.x, acc[3].x); acc[3].y = fmaf(a0.w, wv.y, acc[3].y);
            acc[3].z = fmaf(a0.w, wv.z, acc[3].z); acc[3].w = fmaf(a0.w, wv.w, acc[3].w);
            acc[4].x = fmaf(a1.x, wv.x, acc[4].x); acc[4].y = fmaf(a1.x, wv.y, acc[4].y);
            acc[4].z = fmaf(a1.x, wv.z, acc[4].z); acc[4].w = fmaf(a1.x, wv.w, acc[4].w);
            acc[5].x = fmaf(a1.y, wv.x, acc[5].x); acc[5].y = fmaf(a1.y, wv.y, acc[5].y);
            acc[5].z = fmaf(a1.y, wv.z, acc[5].z); acc[5].w = fmaf(a1.y, wv.w, acc[5].w);
            acc[6].x = fmaf(a1.z, wv.x, acc[6].x); acc[6].y = fmaf(a1.z, wv.y, acc[6].y);
            acc[6].z = fmaf(a1.z, wv.z, acc[6].z); acc[6].w = fmaf(a1.z, wv.w, acc[6].w);
            acc[7].x = fmaf(a1.w, wv.x, acc[7].x); acc[7].y = fmaf(a1.w, wv.y, acc[7].y);
            acc[7].z = fmaf(a1.w, wv.z, acc[7].z); acc[7].w = fmaf(a1.w, wv.w, acc[7].w);
        }
    }
    #pragma unroll
    for (int i = 0; i < 8; i++) {
        int row = br + r0 + i;
        if (row < n_nodes)
            reinterpret_cast<uint2*>(g_msg1)[row * 16 + tx] =
                pack_half4(acc[i].x, acc[i].y, acc[i].z, acc[i].w);
    }
}

// ======================================================================
// Persistent kernel (grid MUST be 592 = 148 SMs x 4 blocks, single wave):
//  phase 1: grid-stride 64-row tiles: CSR gather (msg1) + layer-1 epilogue
//           -> g_h1h, then gemm2 -> g_msg2 (pre-scaled by norm_out)
//  [device barrier]
//  phase 2: layer-2 aggregation + epilogue -> g_msg1 (fp16 pre-BN), BN stats (fp32)
//  [device barrier]
//  phase 3: BN apply: read g_msg1 fp16 -> out fp32
// ======================================================================
__global__ __launch_bounds__(256, 4) void fused_tail_kernel(const float* __restrict__ b1,
                                                            const float* __restrict__ w2,
                                                            const float* __restrict__ b2,
                                                            const float* __restrict__ gamma,
                                                            const float* __restrict__ beta,
                                                            float* __restrict__ out,
                                                            int n_nodes) {
    __shared__ float sHT[64][68];
    __shared__ float sW[64][64];
    __shared__ float sNO[64];    // per-tile norm_out for msg2 epilogue
    int tid = threadIdx.x;
    int tx = tid & 15, ty = tid >> 4;
    int r0 = ty * 4, j0 = tx * 4;
    int lc4 = tid & 15, lr0 = tid >> 4;
    const float sc = scale_const();
    const uint2* __restrict__ m1 = reinterpret_cast<const uint2*>(g_msg1);

    // w2 into smem once (sW untouched across tiles)
    for (int i = tid; i < 1024; i += 256) {
        int k = i >> 4, c = (i & 15) << 2;
        *(float4*)&sW[k][c] = *(const float4*)&w2[k * 64 + c];
    }

    // ---------------- phase 1: gather + gemm2 over 64-row tiles ----------------
    int ntiles = (n_nodes + 63) / 64;
    float4 bv1 = *(const float4*)&b1[lc4 << 2];
    for (int tile = blockIdx.x; tile < ntiles; tile += gridDim.x) {
        int br = tile * 64;
        __syncthreads();   // previous tile's gemm reads done before refill
        if (tid < 64) {
            int row = br + tid;
            sNO[tid] = (row < n_nodes) ? g_norm_out[row] : 0.f;
        }
        #pragma unroll
        for (int t = 0; t < 4; t++) {
            int r = lr0 + t * 16;
            int row = br + r;
            float4 v = make_float4(0.f, 0.f, 0.f, 0.f);
            if (row < n_nodes) {
                int2 rd = g_rowdeg[row];
                int beg = rd.x, end = rd.x + rd.y;
                float4 a0 = make_float4(0.f, 0.f, 0.f, 0.f);
                float4 a1 = make_float4(0.f, 0.f, 0.f, 0.f);
                int e = beg;
                for (; e + 4 <= end; e += 4) {
                    int s0 = g_csr_src[e], s1 = g_csr_src[e + 1];
                    int s2 = g_csr_src[e + 2], s3 = g_csr_src[e + 3];
                    float n0 = g_norm_out[s0], n1 = g_norm_out[s1];
                    float n2 = g_norm_out[s2], n3 = g_norm_out[s3];
                    uint2 u0 = m1[s0 * 16 + lc4];
                    uint2 u1 = m1[s1 * 16 + lc4];
                    uint2 u2 = m1[s2 * 16 + lc4];
                    uint2 u3 = m1[s3 * 16 + lc4];
                    float2 p, q;
                    unpack_half4(u0, p, q);
                    a0.x = fmaf(p.x, n0, a0.x); a0.y = fmaf(p.y, n0, a0.y);
                    a0.z = fmaf(q.x, n0, a0.z); a0.w = fmaf(q.y, n0, a0.w);
                    unpack_half4(u1, p, q);
                    a1.x = fmaf(p.x, n1, a1.x); a1.y = fmaf(p.y, n1, a1.y);
                    a1.z = fmaf(q.x, n1, a1.z); a1.w = fmaf(q.y, n1, a1.w);
                    unpack_half4(u2, p, q);
                    a0.x = fmaf(p.x, n2, a0.x); a0.y = fmaf(p.y, n2, a0.y);
                    a0.z = fmaf(q.x, n2, a0.z); a0.w = fmaf(q.y, n2, a0.w);
                    unpack_half4(u3, p, q);
                    a1.x = fmaf(p.x, n3, a1.x); a1.y = fmaf(p.y, n3, a1.y);
                    a1.z = fmaf(q.x, n3, a1.z); a1.w = fmaf(q.y, n3, a1.w);
                }
                for (; e < end; e++) {
                    int s = g_csr_src[e];
                    float ns = g_norm_out[s];
                    float2 p, q;
                    unpack_half4(m1[s * 16 + lc4], p, q);
                    a0.x = fmaf(p.x, ns, a0.x); a0.y = fmaf(p.y, ns, a0.y);
                    a0.z = fmaf(q.x, ns, a0.z); a0.w = fmaf(q.y, ns, a0.w);
                }
                float ni = g_norm_in[row];
                float2 h0a, h0b;
                unpack_half4(reinterpret_cast<const uint2*>(g_h0h)[row * 16 + lc4], h0a, h0b);
                v.x = (h0a.x + (a0.x + a1.x) * ni + bv1.x) * sc;
                v.y = (h0a.y + (a0.y + a1.y) * ni + bv1.y) * sc;
                v.z = (h0b.x + (a0.z + a1.z) * ni + bv1.z) * sc;
                v.w = (h0b.y + (a0.w + a1.w) * ni + bv1.w) * sc;
                reinterpret_cast<uint2*>(g_h1h)[row * 16 + lc4] = pack_half4(v.x, v.y, v.z, v.w);
            }
            sHT[lc4 * 4 + ((0 + lc4) & 3)][r] = v.x;
            sHT[lc4 * 4 + ((1 + lc4) & 3)][r] = v.y;
            sHT[lc4 * 4 + ((2 + lc4) & 3)][r] = v.z;
            sHT[lc4 * 4 + ((3 + lc4) & 3)][r] = v.w;
        }
        __syncthreads();

        // gemm2: 4 rows x 4 cols per thread
        float4 acc[4];
        #pragma unroll
        for (int i = 0; i < 4; i++) acc[i] = make_float4(0.f, 0.f, 0.f, 0.f);
        #pragma unroll 4
        for (int c = 0; c < 16; c++) {
            #pragma unroll
            for (int j = 0; j < 4; j++) {
                int klog = c * 4 + j;
                int kp   = c * 4 + ((j + c) & 3);
                float4 wv = *(float4*)&sW[klog][j0];
                float4 a0 = *(float4*)&sHT[kp][r0];
                acc[0].x = fmaf(a0.x, wv.x, acc[0].x); acc[0].y = fmaf(a0.x, wv.y, acc[0].y);
                acc[0].z = fmaf(a0.x, wv.z, acc[0].z); acc[0].w = fmaf(a0.x, wv.w, acc[0].w);
                acc[1].x = fmaf(a0.y, wv.x, acc[1].x); acc[1].y = fmaf(a0.y, wv.y, acc[1].y);
                acc[1].z = fmaf(a0.y, wv.z, acc[1].z); acc[1].w = fmaf(a0.y, wv.w, acc[1].w);
                acc[2].x = fmaf(a0.z, wv.x, acc[2].x); acc[2].y = fmaf(a0.z, wv.y, acc[2].y);
                acc[2].z = fmaf(a0.z, wv.z, acc[2].z); acc[2].w = fmaf(a0.z, wv.w, acc[2].w);
                acc[3].x = fmaf(a0.w, wv.x, acc[3].x); acc[3].y = fmaf(a0.w, wv.y, acc[3].y);
                acc[3].z = fmaf(a0.w, wv.z, acc[3].z); acc[3].w = fmaf(a0.w, wv.w, acc[3].w);
            }
        }
        #pragma unroll
        for (int i = 0; i < 4; i++) {
            int row = br + r0 + i;
            if (row < n_nodes) {
                float ns = sNO[r0 + i];
                reinterpret_cast<uint2*>(g_msg2)[row * 16 + tx] =
                    pack_half4(acc[i].x * ns, acc[i].y * ns, acc[i].z * ns, acc[i].w * ns);
            }
        }
    }

    // ---------------- device barrier #1 ----------------
    __threadfence();
    __syncthreads();
    if (tid == 0) {
        atomicAdd(&g_bar, 1u);
        while (atomicAdd(&g_bar, 0u) < gridDim.x) __nanosleep(64);
        __threadfence();
    }
    __syncthreads();

    // ---------------- phase 2: layer-2 aggregation + epilogue -> g_msg1 (fp16) + BN stats ----------------
    __shared__ float ssum[64], ssq[64];
    if (tid < 64) { ssum[tid] = 0.f; ssq[tid] = 0.f; }
    __syncthreads();
    {
        int c = tid & 15;
        float4 bv = reinterpret_cast<const float4*>(b2)[c];
        float4 ls = make_float4(0.f, 0.f, 0.f, 0.f);
        float4 lq = make_float4(0.f, 0.f, 0.f, 0.f);
        const uint2* __restrict__ m2 = reinterpret_cast<const uint2*>(g_msg2);

        for (int node = blockIdx.x * 16 + (tid >> 4); node < n_nodes; node += gridDim.x * 16) {
            int2 rd = g_rowdeg[node];
            int beg = rd.x, end = rd.x + rd.y;
            float4 a0 = make_float4(0.f, 0.f, 0.f, 0.f);
            float4 a1 = make_float4(0.f, 0.f, 0.f, 0.f);
            int e = beg;
            for (; e + 4 <= end; e += 4) {
                int s0 = g_csr_src[e], s1 = g_csr_src[e + 1];
                int s2 = g_csr_src[e + 2], s3 = g_csr_src[e + 3];
                uint2 u0 = m2[s0 * 16 + c];
                uint2 u1 = m2[s1 * 16 + c];
                uint2 u2 = m2[s2 * 16 + c];
                uint2 u3 = m2[s3 * 16 + c];
                float2 p, q;
                unpack_half4(u0, p, q);
                a0.x += p.x; a0.y += p.y; a0.z += q.x; a0.w += q.y;
                unpack_half4(u1, p, q);
                a1.x += p.x; a1.y += p.y; a1.z += q.x; a1.w += q.y;
                unpack_half4(u2, p, q);
                a0.x += p.x; a0.y += p.y; a0.z += q.x; a0.w += q.y;
                unpack_half4(u3, p, q);
                a1.x += p.x; a1.y += p.y; a1.z += q.x; a1.w += q.y;
            }
            for (; e < end; e++) {
                int s = g_csr_src[e];
                float2 p, q;
                unpack_half4(m2[s * 16 + c], p, q);
                a0.x += p.x; a0.y += p.y; a0.z += q.x; a0.w += q.y;
            }
            float ni = g_norm_in[node];
            float2 h1a, h1b;
            unpack_half4(reinterpret_cast<const uint2*>(g_h1h)[node * 16 + c], h1a, h1b);
            float4 h2;
            h2.x = (h1a.x + (a0.x + a1.x) * ni + bv.x) * sc;
            h2.y = (h1a.y + (a0.y + a1.y) * ni + bv.y) * sc;
            h2.z = (h1b.x + (a0.z + a1.z) * ni + bv.z) * sc;
            h2.w = (h1b.y + (a0.w + a1.w) * ni + bv.w) * sc;
            // pre-BN output stored fp16 into reused msg1 buffer
            reinterpret_cast<uint2*>(g_msg1)[node * 16 + c] =
                pack_half4(h2.x, h2.y, h2.z, h2.w);
            // stats from exact fp32 values
            ls.x += h2.x; ls.y += h2.y; ls.z += h2.z; ls.w += h2.w;
            lq.x += h2.x * h2.x; lq.y += h2.y * h2.y; lq.z += h2.z * h2.z; lq.w += h2.w * h2.w;
        }
        atomicAdd(&ssum[c * 4 + 0], ls.x); atomicAdd(&ssq[c * 4 + 0], lq.x);
        atomicAdd(&ssum[c * 4 + 1], ls.y); atomicAdd(&ssq[c * 4 + 1], lq.y);
        atomicAdd(&ssum[c * 4 + 2], ls.z); atomicAdd(&ssq[c * 4 + 2], lq.z);
        atomicAdd(&ssum[c * 4 + 3], ls.w); atomicAdd(&ssq[c * 4 + 3], lq.w);
    }
    __syncthreads();
    if (tid < 64) {
        atomicAdd(&g_stats[tid], ssum[tid]);
        atomicAdd(&g_stats[64 + tid], ssq[tid]);
    }

    // ---------------- device barrier #2 ----------------
    __threadfence();
    __syncthreads();
    if (tid == 0) {
        atomicAdd(&g_bar, 1u);
        while (atomicAdd(&g_bar, 0u) < 2u * gridDim.x) __nanosleep(64);
        __threadfence();
    }
    __syncthreads();

    // ---------------- phase 3: BN apply (fp16 in -> fp32 out) ----------------
    __shared__ float s_scale[64], s_shift[64];
    if (tid < 64) {
        int j = tid;
        volatile float* vs = g_stats;
        float inv_n = 1.f / (float)n_nodes;
        float mu = vs[j] * inv_n;
        float var = vs[64 + j] * inv_n - mu * mu;
        if (var < 0.f) var = 0.f;
        float g = rsqrtf(var + 1e-5f) * gamma[j];
        s_scale[j] = g;
        s_shift[j] = beta[j] - mu * g;
    }
    __syncthreads();
    int total8 = n_nodes * 16;   // uint2 elements (4 halves each)
    int stride = gridDim.x * blockDim.x;
    const uint2* __restrict__ pre = reinterpret_cast<const uint2*>(g_msg1);
    for (int i = blockIdx.x * blockDim.x + tid; i < total8; i += stride) {
        float2 p, q;
        unpack_half4(pre[i], p, q);
        int jj = (i & 15) << 2;
        float4 v;
        v.x = p.x * s_scale[jj + 0] + s_shift[jj + 0];
        v.y = p.y * s_scale[jj + 1] + s_shift[jj + 1];
        v.z = q.x * s_scale[jj + 2] + s_shift[jj + 2];
        v.w = q.y * s_scale[jj + 3] + s_shift[jj + 3];
        reinterpret_cast<float4*>(out)[i] = v;
    }
}

// ---------------- launch ----------------
extern "C" void kernel_launch(void* const* d_in, const int* in_sizes, int n_in,
                              void* d_out, int out_size) {
    const int*   src   = (const int*)d_in[0];
    const int*   dst   = (const int*)d_in[1];
    const float* x     = (const float*)d_in[2];
    const float* fc_w  = (const float*)d_in[3];
    const float* fc_b  = (const float*)d_in[4];
    const float* w1    = (const float*)d_in[5];
    const float* b1    = (const float*)d_in[6];
    const float* w2    = (const float*)d_in[7];
    const float* b2    = (const float*)d_in[8];
    const float* gamma = (const float*)d_in[9];
    const float* beta  = (const float*)d_in[10];
    float* out = (float*)d_out;

    int n_edges = in_sizes[0];
    int n_nodes = in_sizes[2] / 128;

    static cudaStream_t s_build = nullptr;
    static cudaEvent_t ev_fork = nullptr, ev_join = nullptr;
    if (s_build == nullptr) {
        cudaStreamCreateWithFlags(&s_build, cudaStreamNonBlocking);
        cudaEventCreateWithFlags(&ev_fork, cudaEventDisableTiming);
        cudaEventCreateWithFlags(&ev_join, cudaEventDisableTiming);
    }

    cudaEventRecord(ev_fork, 0);
    cudaStreamWaitEvent(s_build, ev_fork, 0);
    zero_all_kernel<<<(n_nodes + 255) / 256, 256, 0, s_build>>>(n_nodes);
    degree_kernel<<<(n_edges + 255) / 256, 256, 0, s_build>>>(src, dst, n_edges);
    finalize_kernel<<<(n_nodes + 255) / 256, 256, 0, s_build>>>(n_nodes);
    bin_kernel<<<(n_edges + 255) / 256, 256, 0, s_build>>>(src, dst, n_edges);
    cudaEventRecord(ev_join, s_build);

    int gblocks = (n_nodes + 127) / 128;
    fcg1_kernel<<<gblocks, 256>>>(x, fc_w, fc_b, w1, n_nodes);

    cudaStreamWaitEvent(0, ev_join, 0);
    fused_tail_kernel<<<592, 256>>>(b1, w2, b2, gamma, beta, out, n_nodes);
}